// round 1
// baseline (speedup 1.0000x reference)
#include <cuda_runtime.h>
#include <cuda_bf16.h>
#include <math.h>

// Problem constants
#define BB   8
#define CC   256
#define CI   128
#define NN   4096   // H*W
#define MM   1024   // (H/2)*(W/2)

// ---------------- scratch (device globals; no allocation allowed) -------------
__device__ float g_conv[(long)BB * 384 * NN];   // [b][o][n], o: 0-127 theta, 128-255 phi, 256-383 g
__device__ float g_phi [(long)BB * CI * MM];    // [b][ci][m]  pooled phi
__device__ float g_gm  [(long)BB * MM * CI];    // [b][m][ci]  pooled g
__device__ float g_f   [(long)BB * NN * MM];    // [b][n][m]   attention scores / softmax
__device__ float g_y   [(long)BB * NN * CI];    // [b][n][ci]
__device__ float g_wy  [(long)BB * CC * NN];    // [b][c][n]
__device__ float g_scale[CC];
__device__ float g_shift[CC];

// ---------------- generic register-tiled SGEMM --------------------------------
// C[m][n] = sum_k A * B (+ bias[m])
// TA: A stored [K][M] row-major (k-major). else A stored [M][K].
// TB: B stored [N][K] row-major.       else B stored [K][N].
// 256 threads. BK = 8. Requires M%BM==0, N%BN==0, K%8==0 (true for all calls).
template<int BM, int BN, int TM, int TN, bool TA, bool TB, bool BIAS>
__global__ __launch_bounds__(256) void sgemm_kernel(
    const float* __restrict__ A, const float* __restrict__ Bm,
    const float* __restrict__ bias, float* __restrict__ C,
    int Mdim, int Ndim, int Kdim,
    long strideA, long strideB, long strideC)
{
    constexpr int BK = 8;
    __shared__ float sA[BK][BM];
    __shared__ float sB[BK][BN];

    const int bz = blockIdx.z;
    A  += (long)bz * strideA;
    Bm += (long)bz * strideB;
    C  += (long)bz * strideC;

    const int mBlock = blockIdx.y * BM;
    const int nBlock = blockIdx.x * BN;
    const int tid = threadIdx.x;

    constexpr int TBN = BN / TN;           // threads along n
    static_assert((256 / TBN) * TM == BM, "tile mapping");
    const int tn = tid % TBN;
    const int tm = tid / TBN;

    float acc[TM][TN];
    #pragma unroll
    for (int i = 0; i < TM; i++)
        #pragma unroll
        for (int j = 0; j < TN; j++) acc[i][j] = 0.f;

    for (int k0 = 0; k0 < Kdim; k0 += BK) {
        // ---- load A tile into sA[k][m] ----
        if (TA) {
            constexpr int rowThreads = BM / 4;
            const int r = tid / rowThreads;
            const int cidx = (tid % rowThreads) * 4;
            constexpr int rstep = 256 / rowThreads;
            #pragma unroll
            for (int rr = r; rr < BK; rr += rstep) {
                float4 v = *(const float4*)&A[(long)(k0 + rr) * Mdim + mBlock + cidx];
                *(float4*)&sA[rr][cidx] = v;
            }
        } else {
            constexpr int rowThreads = BK / 4;     // 2
            const int r = tid / rowThreads;
            const int cidx = (tid % rowThreads) * 4;
            constexpr int rstep = 256 / rowThreads; // 128
            #pragma unroll
            for (int rr = r; rr < BM; rr += rstep) {
                float4 v = *(const float4*)&A[(long)(mBlock + rr) * Kdim + k0 + cidx];
                sA[cidx + 0][rr] = v.x; sA[cidx + 1][rr] = v.y;
                sA[cidx + 2][rr] = v.z; sA[cidx + 3][rr] = v.w;
            }
        }
        // ---- load B tile into sB[k][n] ----
        if (!TB) {
            constexpr int rowThreads = BN / 4;
            const int r = tid / rowThreads;
            const int cidx = (tid % rowThreads) * 4;
            constexpr int rstep = 256 / rowThreads;
            #pragma unroll
            for (int rr = r; rr < BK; rr += rstep) {
                float4 v = *(const float4*)&Bm[(long)(k0 + rr) * Ndim + nBlock + cidx];
                *(float4*)&sB[rr][cidx] = v;
            }
        } else {
            constexpr int rowThreads = BK / 4;      // 2
            const int r = tid / rowThreads;
            const int cidx = (tid % rowThreads) * 4;
            constexpr int rstep = 256 / rowThreads; // 128
            #pragma unroll
            for (int rr = r; rr < BN; rr += rstep) {
                float4 v = *(const float4*)&Bm[(long)(nBlock + rr) * Kdim + k0 + cidx];
                sB[cidx + 0][rr] = v.x; sB[cidx + 1][rr] = v.y;
                sB[cidx + 2][rr] = v.z; sB[cidx + 3][rr] = v.w;
            }
        }
        __syncthreads();

        #pragma unroll
        for (int k = 0; k < BK; k++) {
            float ra[TM], rb[TN];
            #pragma unroll
            for (int i = 0; i < TM; i++) ra[i] = sA[k][tm * TM + i];
            #pragma unroll
            for (int j = 0; j < TN; j++) rb[j] = sB[k][tn * TN + j];
            #pragma unroll
            for (int i = 0; i < TM; i++)
                #pragma unroll
                for (int j = 0; j < TN; j++)
                    acc[i][j] = fmaf(ra[i], rb[j], acc[i][j]);
        }
        __syncthreads();
    }

    // ---- write ----
    #pragma unroll
    for (int i = 0; i < TM; i++) {
        const int mi = mBlock + tm * TM + i;
        const float bv = BIAS ? bias[mi] : 0.f;
        #pragma unroll
        for (int j = 0; j < TN; j += 4) {
            float4 v;
            v.x = acc[i][j + 0] + bv;
            v.y = acc[i][j + 1] + bv;
            v.z = acc[i][j + 2] + bv;
            v.w = acc[i][j + 3] + bv;
            *(float4*)&C[(long)mi * Ndim + nBlock + tn * TN + j] = v;
        }
    }
}

// ---------------- 2x2 maxpool of phi/g conv outputs ---------------------------
__global__ __launch_bounds__(256) void pool_kernel() {
    const int i = blockIdx.x * 256 + threadIdx.x;   // over BB*CI*MM
    if (i >= BB * CI * MM) return;
    const int m  = i & (MM - 1);
    const int ci = (i >> 10) & (CI - 1);
    const int b  = i >> 17;
    const int hp = m >> 5, wp = m & 31;
    const int n0 = hp * 128 + wp * 2;               // (2hp)*64 + 2wp

    const float* pr = g_conv + ((long)b * 384 + 128 + ci) * NN;
    float p = fmaxf(fmaxf(pr[n0], pr[n0 + 1]), fmaxf(pr[n0 + 64], pr[n0 + 65]));
    const float* gr = g_conv + ((long)b * 384 + 256 + ci) * NN;
    float gg = fmaxf(fmaxf(gr[n0], gr[n0 + 1]), fmaxf(gr[n0 + 64], gr[n0 + 65]));

    g_phi[((long)b * CI + ci) * MM + m] = p;
    g_gm [((long)b * MM + m) * CI + ci] = gg;
}

// ---------------- row softmax over M=1024 -------------------------------------
__global__ __launch_bounds__(256) void softmax_kernel() {
    float* row = g_f + (long)blockIdx.x * MM;
    const int t = threadIdx.x;
    float4 v = ((float4*)row)[t];

    float mx = fmaxf(fmaxf(v.x, v.y), fmaxf(v.z, v.w));
    #pragma unroll
    for (int o = 16; o; o >>= 1) mx = fmaxf(mx, __shfl_xor_sync(0xffffffffu, mx, o));
    __shared__ float sm[8];
    const int w = t >> 5, l = t & 31;
    if (l == 0) sm[w] = mx;
    __syncthreads();
    mx = sm[0];
    #pragma unroll
    for (int i = 1; i < 8; i++) mx = fmaxf(mx, sm[i]);
    __syncthreads();

    v.x = __expf(v.x - mx); v.y = __expf(v.y - mx);
    v.z = __expf(v.z - mx); v.w = __expf(v.w - mx);
    float s = v.x + v.y + v.z + v.w;
    #pragma unroll
    for (int o = 16; o; o >>= 1) s += __shfl_xor_sync(0xffffffffu, s, o);
    if (l == 0) sm[w] = s;
    __syncthreads();
    s = 0.f;
    #pragma unroll
    for (int i = 0; i < 8; i++) s += sm[i];
    const float inv = 1.f / s;
    v.x *= inv; v.y *= inv; v.z *= inv; v.w *= inv;
    ((float4*)row)[t] = v;
}

// ---------------- BN statistics (deterministic tree reduce) -------------------
__global__ __launch_bounds__(256) void bn_stats_kernel(const float* __restrict__ gamma,
                                                       const float* __restrict__ beta) {
    const int c = blockIdx.x;
    const int t = threadIdx.x;
    double s = 0.0, sq = 0.0;
    for (int i = t; i < BB * NN; i += 256) {
        const int b = i >> 12;
        const int n = i & (NN - 1);
        const float v = g_wy[(((long)b * CC + c) << 12) + n];
        s += (double)v;
        sq += (double)v * (double)v;
    }
    __shared__ double ss[256], sz[256];
    ss[t] = s; sz[t] = sq;
    __syncthreads();
    for (int st = 128; st; st >>= 1) {
        if (t < st) { ss[t] += ss[t + st]; sz[t] += sz[t + st]; }
        __syncthreads();
    }
    if (t == 0) {
        const double cnt = 1.0 / (double)(BB * NN);
        const double mean = ss[0] * cnt;
        const double var  = sz[0] * cnt - mean * mean;
        const double inv  = 1.0 / sqrt(var + 1e-5);
        const float sc = gamma[c] * (float)inv;
        g_scale[c] = sc;
        g_shift[c] = beta[c] - (float)mean * sc;
    }
}

// ---------------- apply BN + residual -----------------------------------------
__global__ __launch_bounds__(256) void final_kernel(const float* __restrict__ x,
                                                    float* __restrict__ out) {
    const long i = (long)blockIdx.x * 256 + threadIdx.x;  // float4 index over BB*CC*NN/4
    const long e = i << 2;
    const int c = (int)((e >> 12) & (CC - 1));
    const float sc = g_scale[c], sh = g_shift[c];
    float4 wy = ((const float4*)g_wy)[i];
    float4 xv = ((const float4*)x)[i];
    float4 o;
    o.x = fmaf(wy.x, sc, sh) + xv.x;
    o.y = fmaf(wy.y, sc, sh) + xv.y;
    o.z = fmaf(wy.z, sc, sh) + xv.z;
    o.w = fmaf(wy.w, sc, sh) + xv.w;
    ((float4*)out)[i] = o;
}

// ------------------------------------------------------------------------------
extern "C" void kernel_launch(void* const* d_in, const int* in_sizes, int n_in,
                              void* d_out, int out_size) {
    (void)in_sizes; (void)n_in; (void)out_size;
    const float* x     = (const float*)d_in[0];
    const float* tw    = (const float*)d_in[1];
    const float* tb    = (const float*)d_in[2];
    const float* pw    = (const float*)d_in[3];
    const float* pb    = (const float*)d_in[4];
    const float* gw    = (const float*)d_in[5];
    const float* gb    = (const float*)d_in[6];
    const float* Ww    = (const float*)d_in[7];
    const float* Wb    = (const float*)d_in[8];
    const float* gamma = (const float*)d_in[9];
    const float* beta  = (const float*)d_in[10];
    float* out = (float*)d_out;

    float *conv, *phi, *gm, *f, *y, *wy;
    cudaGetSymbolAddress((void**)&conv, g_conv);
    cudaGetSymbolAddress((void**)&phi,  g_phi);
    cudaGetSymbolAddress((void**)&gm,   g_gm);
    cudaGetSymbolAddress((void**)&f,    g_f);
    cudaGetSymbolAddress((void**)&y,    g_y);
    cudaGetSymbolAddress((void**)&wy,   g_wy);

    // K1: three 1x1 convs.  out[b][o][n] = sum_c W[o][c] * x[b][c][n] + b[o]
    // A = weight [128][256] (shared across batch), B = x [256][4096]
    {
        dim3 grid(NN / 128, 1, BB);
        sgemm_kernel<128,128,8,8,false,false,true><<<grid, 256>>>(
            tw, x, tb, conv,                 128, NN, CC, 0, (long)CC * NN, (long)384 * NN);
        sgemm_kernel<128,128,8,8,false,false,true><<<grid, 256>>>(
            pw, x, pb, conv + (long)128 * NN, 128, NN, CC, 0, (long)CC * NN, (long)384 * NN);
        sgemm_kernel<128,128,8,8,false,false,true><<<grid, 256>>>(
            gw, x, gb, conv + (long)256 * NN, 128, NN, CC, 0, (long)CC * NN, (long)384 * NN);
    }

    // K2: 2x2 maxpool for phi and g
    pool_kernel<<<(BB * CI * MM + 255) / 256, 256>>>();

    // K3a: f[b][n][m] = sum_ci theta[b][ci][n] * phi[b][ci][m]
    // A = theta (k-major [ci][n], stride = Mdim = 4096), B = phi [ci][m]
    sgemm_kernel<128,128,8,8,true,false,false><<<dim3(MM / 128, NN / 128, BB), 256>>>(
        conv, phi, nullptr, f, NN, MM, CI,
        (long)384 * NN, (long)CI * MM, (long)NN * MM);

    // K3b: softmax over m
    softmax_kernel<<<BB * NN, 256>>>();

    // K3c: y[b][n][ci] = sum_m f[b][n][m] * g[b][m][ci]
    sgemm_kernel<128,64,8,4,false,false,false><<<dim3(CI / 64, NN / 128, BB), 256>>>(
        f, gm, nullptr, y, NN, CI, MM,
        (long)NN * MM, (long)MM * CI, (long)NN * CI);

    // K4: Wy[b][c][n] = sum_ci Ww[c][ci] * y[b][n][ci] + Wb[c]   (B transposed layout)
    sgemm_kernel<128,128,8,8,false,true,true><<<dim3(NN / 128, CC / 128, BB), 256>>>(
        Ww, y, Wb, wy, CC, NN, CI,
        0, (long)NN * CI, (long)CC * NN);

    // K5: BN statistics per channel
    bn_stats_kernel<<<CC, 256>>>(gamma, beta);

    // K6: apply BN + residual
    final_kernel<<<(BB * CC * NN) / 4 / 256, 256>>>(x, out);
}

// round 4
// speedup vs baseline: 1.0880x; 1.0880x over previous
#include <cuda_runtime.h>
#include <cuda_bf16.h>
#include <math.h>
#include <stdint.h>

// Problem constants
#define BB   8
#define CC   256
#define CI   128
#define NN   4096   // H*W
#define MM   1024   // (H/2)*(W/2)

// ---------------- scratch (device globals; no allocation allowed) -------------
__device__ float g_conv[(long)BB * 384 * NN];   // [b][o][n]: 0-127 theta, 128-255 phi(raw), 256-383 g(raw)
__device__ float g_phi [(long)BB * CI * MM];    // [b][ci][m]  pooled phi
__device__ float g_gp  [(long)BB * CI * MM];    // [b][ci][m]  pooled g (channel-major)
__device__ float g_f   [(long)BB * NN * MM];    // [b][n][m]
__device__ float g_y   [(long)BB * NN * CI];    // [b][n][ci]
__device__ float g_wy  [(long)BB * CC * NN];    // [b][c][n]
__device__ float g_scale[CC];
__device__ float g_shift[CC];

#define SWZ128(off) ((off) ^ (((off) >> 3) & 0x70))

// ---------------- mma.sync + ldmatrix wrappers --------------------------------
__device__ __forceinline__ uint32_t smem_u32(const void* p) {
    uint32_t a;
    asm("{ .reg .u64 t; cvta.to.shared.u64 t, %1; cvt.u32.u64 %0, t; }" : "=r"(a) : "l"(p));
    return a;
}

#define LDSM_X4(r0, r1, r2, r3, addr) \
    asm volatile("ldmatrix.sync.aligned.m8n8.x4.shared.b16 {%0,%1,%2,%3}, [%4];" \
                 : "=r"(r0), "=r"(r1), "=r"(r2), "=r"(r3) : "r"(addr))
#define LDSM_X2(r0, r1, addr) \
    asm volatile("ldmatrix.sync.aligned.m8n8.x2.shared.b16 {%0,%1}, [%2];" \
                 : "=r"(r0), "=r"(r1) : "r"(addr))

__device__ __forceinline__ void mma16816(float* c, uint32_t a0, uint32_t a1, uint32_t a2, uint32_t a3,
                                         uint32_t b0, uint32_t b1) {
    asm volatile(
        "mma.sync.aligned.m16n8k16.row.col.f32.bf16.bf16.f32 "
        "{%0,%1,%2,%3}, {%4,%5,%6,%7}, {%8,%9}, {%0,%1,%2,%3};"
        : "+f"(c[0]), "+f"(c[1]), "+f"(c[2]), "+f"(c[3])
        : "r"(a0), "r"(a1), "r"(a2), "r"(a3), "r"(b0), "r"(b1));
}

// =====================  SMEM fill: fp32 -> bf16 hi/lo split  ==================
// Produces a 128-row x 64-k bf16 tile (128B rows) with SW128 swizzle at offHi/offLo.
__device__ __forceinline__ void fill_kcontig(const float* base, long ld, int rowBlock, int k0,
                                             char* sm, uint32_t offHi, uint32_t offLo, int tid) {
    #pragma unroll
    for (int it = 0; it < 8; it++) {
        int idx = it * 256 + tid;      // 0..2047 float4s over 128 rows x 64 k
        int row = idx >> 4;
        int k4  = (idx & 15) << 2;
        float4 v = *(const float4*)(base + (long)(rowBlock + row) * ld + k0 + k4);
        __nv_bfloat16 h0 = __float2bfloat16(v.x);
        __nv_bfloat16 h1 = __float2bfloat16(v.y);
        __nv_bfloat16 h2 = __float2bfloat16(v.z);
        __nv_bfloat16 h3 = __float2bfloat16(v.w);
        __nv_bfloat16 l0 = __float2bfloat16(v.x - __bfloat162float(h0));
        __nv_bfloat16 l1 = __float2bfloat16(v.y - __bfloat162float(h1));
        __nv_bfloat16 l2 = __float2bfloat16(v.z - __bfloat162float(h2));
        __nv_bfloat16 l3 = __float2bfloat16(v.w - __bfloat162float(h3));
        uint32_t off = (uint32_t)(row * 128 + (k4 << 1));
        uint32_t sw = SWZ128(off);
        *(__nv_bfloat162*)(sm + offHi + sw)     = __nv_bfloat162(h0, h1);
        *(__nv_bfloat162*)(sm + offHi + sw + 4) = __nv_bfloat162(h2, h3);
        *(__nv_bfloat162*)(sm + offLo + sw)     = __nv_bfloat162(l0, l1);
        *(__nv_bfloat162*)(sm + offLo + sw + 4) = __nv_bfloat162(l2, l3);
    }
}

__device__ __forceinline__ void fill_trans(const float* base, long ld, int rowBlock, int k0,
                                           char* sm, uint32_t offHi, uint32_t offLo, int tid) {
    #pragma unroll
    for (int it = 0; it < 8; it++) {
        int idx = it * 256 + tid;      // 0..2047 float4s over 64 k x 128 rows (k-major source)
        int kk  = idx >> 5;
        int m4  = (idx & 31) << 2;
        float4 v = *(const float4*)(base + (long)(k0 + kk) * ld + rowBlock + m4);
        float va[4] = {v.x, v.y, v.z, v.w};
        #pragma unroll
        for (int e = 0; e < 4; e++) {
            int row = m4 + e;
            __nv_bfloat16 h = __float2bfloat16(va[e]);
            __nv_bfloat16 l = __float2bfloat16(va[e] - __bfloat162float(h));
            uint32_t sw = SWZ128((uint32_t)(row * 128 + (kk << 1)));
            *(__nv_bfloat16*)(sm + offHi + sw) = h;
            *(__nv_bfloat16*)(sm + offLo + sw) = l;
        }
    }
}

// =====================  templated tensor-core GEMM  ===========================
// C[M][N] (+bias[M]) = sum_k A*B. 128x128 CTA tile, 8 warps (64x32 each), K chunk 64.
// TA/TB: operand stored [K][rows] (transpose-on-load); else [rows][K] k-contiguous.
#define SMEM_GEMM_BYTES (4 * 16384)

template<bool TA, bool TB, bool BIAS>
__global__ __launch_bounds__(256) void gemm_tc(
    const float* __restrict__ A, const float* __restrict__ Bm,
    const float* __restrict__ bias, float* __restrict__ C,
    int ldA, int ldB, int ldC, int K,
    long strideA, long strideB, long strideC)
{
    extern __shared__ __align__(1024) char sm[];
    const int bz = blockIdx.z;
    A  += (long)bz * strideA;
    Bm += (long)bz * strideB;
    C  += (long)bz * strideC;
    const int mBlock = blockIdx.y * 128;
    const int nBlock = blockIdx.x * 128;
    const int tid = threadIdx.x;
    const int wid = tid >> 5;
    const int lane = tid & 31;

    const uint32_t sbase = smem_u32(sm);
    const uint32_t OFF_AH = 0;
    const uint32_t OFF_AL = 16384;
    const uint32_t OFF_BH = 32768;
    const uint32_t OFF_BL = 49152;

    // warp tile: 64 (M) x 32 (N)
    const int mWarp = (wid >> 2) * 64;
    const int nWarp = (wid & 3) * 32;

    float acc[4][4][4];
    #pragma unroll
    for (int i = 0; i < 4; i++)
        #pragma unroll
        for (int j = 0; j < 4; j++)
            #pragma unroll
            for (int r = 0; r < 4; r++) acc[i][j][r] = 0.f;

    // ldmatrix lane-address components (byte offsets within a 128B-row tile)
    // A: row = mWarp + mi*16 + (lane&15); kByte = ks*32 + (lane>>4)*16
    const int aRow = mWarp + (lane & 15);
    const int aKb  = (lane >> 4) << 4;
    // B: row = nWarp + ni*8 + (lane&7); kByte = ks*32 + ((lane>>3)&1)*16
    const int bRow = nWarp + (lane & 7);
    const int bKb  = ((lane >> 3) & 1) << 4;

    const int nChunks = K >> 6;
    for (int ch = 0; ch < nChunks; ch++) {
        const int k0 = ch << 6;
        if (TA) fill_trans (A, ldA, mBlock, k0, sm, OFF_AH, OFF_AL, tid);
        else    fill_kcontig(A, ldA, mBlock, k0, sm, OFF_AH, OFF_AL, tid);
        if (TB) fill_trans (Bm, ldB, nBlock, k0, sm, OFF_BH, OFF_BL, tid);
        else    fill_kcontig(Bm, ldB, nBlock, k0, sm, OFF_BH, OFF_BL, tid);
        __syncthreads();

        #pragma unroll
        for (int ks = 0; ks < 4; ks++) {
            uint32_t aH[4][4], aL[4][4];
            #pragma unroll
            for (int mi = 0; mi < 4; mi++) {
                uint32_t off = (uint32_t)((aRow + mi * 16) * 128 + ks * 32 + aKb);
                uint32_t sw = SWZ128(off);
                LDSM_X4(aH[mi][0], aH[mi][1], aH[mi][2], aH[mi][3], sbase + OFF_AH + sw);
                LDSM_X4(aL[mi][0], aL[mi][1], aL[mi][2], aL[mi][3], sbase + OFF_AL + sw);
            }
            #pragma unroll
            for (int ni = 0; ni < 4; ni++) {
                uint32_t off = (uint32_t)((bRow + ni * 8) * 128 + ks * 32 + bKb);
                uint32_t sw = SWZ128(off);
                uint32_t bH0, bH1, bL0, bL1;
                LDSM_X2(bH0, bH1, sbase + OFF_BH + sw);
                LDSM_X2(bL0, bL1, sbase + OFF_BL + sw);
                #pragma unroll
                for (int mi = 0; mi < 4; mi++) {
                    mma16816(acc[mi][ni], aH[mi][0], aH[mi][1], aH[mi][2], aH[mi][3], bH0, bH1);
                    mma16816(acc[mi][ni], aH[mi][0], aH[mi][1], aH[mi][2], aH[mi][3], bL0, bL1);
                    mma16816(acc[mi][ni], aL[mi][0], aL[mi][1], aL[mi][2], aL[mi][3], bH0, bH1);
                }
            }
        }
        __syncthreads();
    }

    // ---- epilogue ----
    const int mLane = lane >> 2;          // 0..7
    const int nLane = (lane & 3) * 2;     // 0,2,4,6
    #pragma unroll
    for (int mi = 0; mi < 4; mi++) {
        const int m0 = mBlock + mWarp + mi * 16 + mLane;
        const float bv0 = BIAS ? bias[m0] : 0.f;
        const float bv1 = BIAS ? bias[m0 + 8] : 0.f;
        #pragma unroll
        for (int ni = 0; ni < 4; ni++) {
            const int n = nBlock + nWarp + ni * 8 + nLane;
            float2 v0, v1;
            v0.x = acc[mi][ni][0] + bv0; v0.y = acc[mi][ni][1] + bv0;
            v1.x = acc[mi][ni][2] + bv1; v1.y = acc[mi][ni][3] + bv1;
            *(float2*)&C[(long)m0 * ldC + n]       = v0;
            *(float2*)&C[(long)(m0 + 8) * ldC + n] = v1;
        }
    }
}

// ---------------- 2x2 maxpool of phi/g conv outputs ---------------------------
__global__ __launch_bounds__(256) void pool_kernel() {
    const int i = blockIdx.x * 256 + threadIdx.x;   // over BB*CI*MM
    if (i >= BB * CI * MM) return;
    const int m  = i & (MM - 1);
    const int ci = (i >> 10) & (CI - 1);
    const int b  = i >> 17;
    const int hp = m >> 5, wp = m & 31;
    const int n0 = hp * 128 + wp * 2;

    const float* pr = g_conv + ((long)b * 384 + 128 + ci) * NN;
    float p = fmaxf(fmaxf(pr[n0], pr[n0 + 1]), fmaxf(pr[n0 + 64], pr[n0 + 65]));
    const float* gr = g_conv + ((long)b * 384 + 256 + ci) * NN;
    float gg = fmaxf(fmaxf(gr[n0], gr[n0 + 1]), fmaxf(gr[n0 + 64], gr[n0 + 65]));

    g_phi[((long)b * CI + ci) * MM + m] = p;
    g_gp [((long)b * CI + ci) * MM + m] = gg;
}

// ---------------- row softmax over M=1024 -------------------------------------
__global__ __launch_bounds__(256) void softmax_kernel() {
    float* row = g_f + (long)blockIdx.x * MM;
    const int t = threadIdx.x;
    float4 v = ((float4*)row)[t];

    float mx = fmaxf(fmaxf(v.x, v.y), fmaxf(v.z, v.w));
    #pragma unroll
    for (int o = 16; o; o >>= 1) mx = fmaxf(mx, __shfl_xor_sync(0xffffffffu, mx, o));
    __shared__ float smv[8];
    const int w = t >> 5, l = t & 31;
    if (l == 0) smv[w] = mx;
    __syncthreads();
    mx = smv[0];
    #pragma unroll
    for (int i = 1; i < 8; i++) mx = fmaxf(mx, smv[i]);
    __syncthreads();

    v.x = __expf(v.x - mx); v.y = __expf(v.y - mx);
    v.z = __expf(v.z - mx); v.w = __expf(v.w - mx);
    float s = v.x + v.y + v.z + v.w;
    #pragma unroll
    for (int o = 16; o; o >>= 1) s += __shfl_xor_sync(0xffffffffu, s, o);
    if (l == 0) smv[w] = s;
    __syncthreads();
    s = 0.f;
    #pragma unroll
    for (int i = 0; i < 8; i++) s += smv[i];
    const float inv = 1.f / s;
    v.x *= inv; v.y *= inv; v.z *= inv; v.w *= inv;
    ((float4*)row)[t] = v;
}

// ---------------- BN statistics (deterministic tree reduce) -------------------
__global__ __launch_bounds__(256) void bn_stats_kernel(const float* __restrict__ gamma,
                                                       const float* __restrict__ beta) {
    const int c = blockIdx.x;
    const int t = threadIdx.x;
    double s = 0.0, sq = 0.0;
    for (int i = t; i < BB * NN; i += 256) {
        const int b = i >> 12;
        const int n = i & (NN - 1);
        const float v = g_wy[(((long)b * CC + c) << 12) + n];
        s += (double)v;
        sq += (double)v * (double)v;
    }
    __shared__ double ss[256], sz[256];
    ss[t] = s; sz[t] = sq;
    __syncthreads();
    for (int st = 128; st; st >>= 1) {
        if (t < st) { ss[t] += ss[t + st]; sz[t] += sz[t + st]; }
        __syncthreads();
    }
    if (t == 0) {
        const double cnt = 1.0 / (double)(BB * NN);
        const double mean = ss[0] * cnt;
        const double var  = sz[0] * cnt - mean * mean;
        const double inv  = 1.0 / sqrt(var + 1e-5);
        const float sc = gamma[c] * (float)inv;
        g_scale[c] = sc;
        g_shift[c] = beta[c] - (float)mean * sc;
    }
}

// ---------------- apply BN + residual -----------------------------------------
__global__ __launch_bounds__(256) void final_kernel(const float* __restrict__ x,
                                                    float* __restrict__ out) {
    const long i = (long)blockIdx.x * 256 + threadIdx.x;
    const long e = i << 2;
    const int c = (int)((e >> 12) & (CC - 1));
    const float sc = g_scale[c], sh = g_shift[c];
    float4 wy = ((const float4*)g_wy)[i];
    float4 xv = ((const float4*)x)[i];
    float4 o;
    o.x = fmaf(wy.x, sc, sh) + xv.x;
    o.y = fmaf(wy.y, sc, sh) + xv.y;
    o.z = fmaf(wy.z, sc, sh) + xv.z;
    o.w = fmaf(wy.w, sc, sh) + xv.w;
    ((float4*)out)[i] = o;
}

// ------------------------------------------------------------------------------
extern "C" void kernel_launch(void* const* d_in, const int* in_sizes, int n_in,
                              void* d_out, int out_size) {
    (void)in_sizes; (void)n_in; (void)out_size;
    const float* x     = (const float*)d_in[0];
    const float* tw    = (const float*)d_in[1];
    const float* tb    = (const float*)d_in[2];
    const float* pw    = (const float*)d_in[3];
    const float* pb    = (const float*)d_in[4];
    const float* gw    = (const float*)d_in[5];
    const float* gb    = (const float*)d_in[6];
    const float* Ww    = (const float*)d_in[7];
    const float* Wb    = (const float*)d_in[8];
    const float* gamma = (const float*)d_in[9];
    const float* beta  = (const float*)d_in[10];
    float* out = (float*)d_out;

    float *conv, *phi, *gp, *f, *y, *wy;
    cudaGetSymbolAddress((void**)&conv, g_conv);
    cudaGetSymbolAddress((void**)&phi,  g_phi);
    cudaGetSymbolAddress((void**)&gp,   g_gp);
    cudaGetSymbolAddress((void**)&f,    g_f);
    cudaGetSymbolAddress((void**)&y,    g_y);
    cudaGetSymbolAddress((void**)&wy,   g_wy);

    cudaFuncSetAttribute(gemm_tc<false, true,  true >, cudaFuncAttributeMaxDynamicSharedMemorySize, SMEM_GEMM_BYTES);
    cudaFuncSetAttribute(gemm_tc<true,  true,  false>, cudaFuncAttributeMaxDynamicSharedMemorySize, SMEM_GEMM_BYTES);
    cudaFuncSetAttribute(gemm_tc<false, false, false>, cudaFuncAttributeMaxDynamicSharedMemorySize, SMEM_GEMM_BYTES);
    cudaFuncSetAttribute(gemm_tc<false, false, true >, cudaFuncAttributeMaxDynamicSharedMemorySize, SMEM_GEMM_BYTES);

    // K1: three 1x1 convs. C[o][n] = sum_c W[o][c]*x[c][n] + b[o]
    // A = W [128][256] k-contig (ldA=256), B = x stored [c][n] -> TB transpose (ldB=4096)
    {
        dim3 grid(NN / 128, 1, BB);
        gemm_tc<false, true, true><<<grid, 256, SMEM_GEMM_BYTES>>>(
            tw, x, tb, conv,                  CC, NN, NN, CC, 0, (long)CC * NN, (long)384 * NN);
        gemm_tc<false, true, true><<<grid, 256, SMEM_GEMM_BYTES>>>(
            pw, x, pb, conv + (long)128 * NN, CC, NN, NN, CC, 0, (long)CC * NN, (long)384 * NN);
        gemm_tc<false, true, true><<<grid, 256, SMEM_GEMM_BYTES>>>(
            gw, x, gb, conv + (long)256 * NN, CC, NN, NN, CC, 0, (long)CC * NN, (long)384 * NN);
    }

    // K2: 2x2 maxpool for phi and g
    pool_kernel<<<(BB * CI * MM + 255) / 256, 256>>>();

    // K3a: f[n][m] = sum_ci theta[ci][n] * phi[ci][m]  (both operands k-major -> TA, TB)
    gemm_tc<true, true, false><<<dim3(MM / 128, NN / 128, BB), 256, SMEM_GEMM_BYTES>>>(
        conv, phi, nullptr, f, NN, MM, MM, CI,
        (long)384 * NN, (long)CI * MM, (long)NN * MM);

    // K3b: softmax over m
    softmax_kernel<<<BB * NN, 256>>>();

    // K3c: y[n][ci] = sum_m f[n][m] * g[ci][m]  (both k-contiguous)
    gemm_tc<false, false, false><<<dim3(CI / 128, NN / 128, BB), 256, SMEM_GEMM_BYTES>>>(
        f, gp, nullptr, y, MM, MM, CI, MM,
        (long)NN * MM, (long)CI * MM, (long)NN * CI);

    // K4: wy[c][n] = sum_ci Ww[c][ci] * y[n][ci]  (both k-contiguous)
    gemm_tc<false, false, true><<<dim3(NN / 128, CC / 128, BB), 256, SMEM_GEMM_BYTES>>>(
        Ww, y, Wb, wy, CI, CI, NN, CI,
        0, (long)NN * CI, (long)CC * NN);

    // K5: BN statistics per channel
    bn_stats_kernel<<<CC, 256>>>(gamma, beta);

    // K6: apply BN + residual
    final_kernel<<<(BB * CC * NN) / 4 / 256, 256>>>(x, out);
}

// round 5
// speedup vs baseline: 2.0963x; 1.9267x over previous
#include <cuda_runtime.h>
#include <cuda_bf16.h>
#include <math.h>
#include <stdint.h>

#define BB 8
#define CC 256
#define CI 128
#define NN 4096
#define MM 1024

// ---------------- device-global scratch (no allocation allowed) ---------------
__device__ __align__(16) __nv_bfloat16 g_xT_hi[(long)BB * NN * CC];
__device__ __align__(16) __nv_bfloat16 g_xT_lo[(long)BB * NN * CC];
__device__ __align__(16) __nv_bfloat16 g_w_hi[384 * CC + CC * CI];   // wcat[384][256] then Ww[256][128]
__device__ __align__(16) __nv_bfloat16 g_w_lo[384 * CC + CC * CI];
__device__ float g_bias384[384];
__device__ __align__(16) __nv_bfloat16 g_o3_hi[(long)BB * NN * 384]; // [b][n][384]: theta|phi|g
__device__ __align__(16) __nv_bfloat16 g_o3_lo[(long)BB * NN * 384];
__device__ __align__(16) __nv_bfloat16 g_phi_hi[(long)BB * MM * CI]; // [b][m][ci]
__device__ __align__(16) __nv_bfloat16 g_phi_lo[(long)BB * MM * CI];
__device__ __align__(16) __nv_bfloat16 g_gT_hi[(long)BB * CI * MM];  // [b][ci][m]
__device__ __align__(16) __nv_bfloat16 g_gT_lo[(long)BB * CI * MM];
__device__ float g_f[(long)BB * NN * MM];
__device__ __align__(16) __nv_bfloat16 g_f_hi[(long)BB * NN * MM];
__device__ __align__(16) __nv_bfloat16 g_f_lo[(long)BB * NN * MM];
__device__ __align__(16) __nv_bfloat16 g_y_hi[(long)BB * NN * CI];
__device__ __align__(16) __nv_bfloat16 g_y_lo[(long)BB * NN * CI];
__device__ float g_wy[(long)BB * CC * NN];
__device__ float g_scale[CC], g_shift[CC];

#define SWZ128(off) ((off) ^ (((off) >> 3) & 0x70))

// ---------------- PTX wrappers ------------------------------------------------
__device__ __forceinline__ uint32_t smem_u32(const void* p) {
    uint32_t a;
    asm("{ .reg .u64 t; cvta.to.shared.u64 t, %1; cvt.u32.u64 %0, t; }" : "=r"(a) : "l"(p));
    return a;
}
#define LDSM_X4(r0, r1, r2, r3, addr) \
    asm volatile("ldmatrix.sync.aligned.m8n8.x4.shared.b16 {%0,%1,%2,%3}, [%4];" \
                 : "=r"(r0), "=r"(r1), "=r"(r2), "=r"(r3) : "r"(addr))
#define LDSM_X2(r0, r1, addr) \
    asm volatile("ldmatrix.sync.aligned.m8n8.x2.shared.b16 {%0,%1}, [%2];" \
                 : "=r"(r0), "=r"(r1) : "r"(addr))
__device__ __forceinline__ void mma16816(float* c, uint32_t a0, uint32_t a1, uint32_t a2, uint32_t a3,
                                         uint32_t b0, uint32_t b1) {
    asm volatile(
        "mma.sync.aligned.m16n8k16.row.col.f32.bf16.bf16.f32 "
        "{%0,%1,%2,%3}, {%4,%5,%6,%7}, {%8,%9}, {%0,%1,%2,%3};"
        : "+f"(c[0]), "+f"(c[1]), "+f"(c[2]), "+f"(c[3])
        : "r"(a0), "r"(a1), "r"(a2), "r"(a3), "r"(b0), "r"(b1));
}
__device__ __forceinline__ void cpa16(uint32_t dst, const void* src) {
    asm volatile("cp.async.cg.shared.global [%0], [%1], 16;" :: "r"(dst), "l"(src));
}
#define CP_COMMIT() asm volatile("cp.async.commit_group;")
#define CP_WAIT1()  asm volatile("cp.async.wait_group 1;")

// ---------------- hi/lo split helpers -----------------------------------------
__device__ __forceinline__ void split2(float v, __nv_bfloat16& h, __nv_bfloat16& l) {
    h = __float2bfloat16(v);
    l = __float2bfloat16(v - __bfloat162float(h));
}

// =====================  bf16 hi/lo pipelined tensor-core GEMM  ================
// C[M][N] = sum_k A*B (+bias). Operands bf16 hi/lo, k-contiguous rows.
// 128x128 CTA tile, 8 warps (64x32), K-chunk 64, 2-stage cp.async pipeline.
// BIAS_MODE: 0 none, 1 per-row, 2 per-col. OUT_BF16: write hi/lo bf16 arrays.
#define STAGE_BYTES 65536
#define SMEM_GEMM_BYTES (2 * STAGE_BYTES)

__device__ __forceinline__ void load_op(const __nv_bfloat16* hi, const __nv_bfloat16* lo,
                                        int rowBase, int ld, int k0,
                                        uint32_t smH, uint32_t smL, int tid) {
    #pragma unroll
    for (int it = 0; it < 4; it++) {
        int idx = it * 256 + tid;       // 1024 16B segs over 128 rows x 128B
        int r = idx >> 3, s = idx & 7;
        uint32_t sw = SWZ128((uint32_t)(r * 128 + s * 16));
        const __nv_bfloat16* gh = hi + (long)(rowBase + r) * ld + k0 + s * 8;
        const __nv_bfloat16* gl = lo + (long)(rowBase + r) * ld + k0 + s * 8;
        cpa16(smH + sw, gh);
        cpa16(smL + sw, gl);
    }
}

template<int BIAS_MODE, bool OUT_BF16>
__global__ __launch_bounds__(256) void gemm_bf16(
    const __nv_bfloat16* __restrict__ Ahi, const __nv_bfloat16* __restrict__ Alo,
    const __nv_bfloat16* __restrict__ Bhi, const __nv_bfloat16* __restrict__ Blo,
    const float* __restrict__ bias,
    float* __restrict__ Cf, __nv_bfloat16* __restrict__ Chi, __nv_bfloat16* __restrict__ Clo,
    int ldA, int ldB, int ldC, int K,
    long sA, long sB, long sC)
{
    extern __shared__ __align__(1024) char sm[];
    const int bz = blockIdx.z;
    Ahi += (long)bz * sA; Alo += (long)bz * sA;
    Bhi += (long)bz * sB; Blo += (long)bz * sB;
    const long coff = (long)bz * sC;

    const int mBlock = blockIdx.y * 128;
    const int nBlock = blockIdx.x * 128;
    const int tid = threadIdx.x;
    const int wid = tid >> 5;
    const int lane = tid & 31;
    const uint32_t sbase = smem_u32(sm);

    const int mWarp = (wid >> 2) * 64;
    const int nWarp = (wid & 3) * 32;

    float acc[4][4][4];
    #pragma unroll
    for (int i = 0; i < 4; i++)
        #pragma unroll
        for (int j = 0; j < 4; j++)
            #pragma unroll
            for (int r = 0; r < 4; r++) acc[i][j][r] = 0.f;

    const int aRow = mWarp + (lane & 15);
    const int aKb  = (lane >> 4) << 4;
    const int bRow = nWarp + (lane & 7);
    const int bKb  = ((lane >> 3) & 1) << 4;

    const int nChunks = K >> 6;
    // prologue: stage 0
    load_op(Ahi, Alo, mBlock, ldA, 0, sbase + 0,     sbase + 16384, tid);
    load_op(Bhi, Blo, nBlock, ldB, 0, sbase + 32768, sbase + 49152, tid);
    CP_COMMIT();

    for (int ch = 0; ch < nChunks; ch++) {
        if (ch + 1 < nChunks) {
            const uint32_t sb = sbase + ((ch + 1) & 1) * STAGE_BYTES;
            const int k0 = (ch + 1) << 6;
            load_op(Ahi, Alo, mBlock, ldA, k0, sb + 0,     sb + 16384, tid);
            load_op(Bhi, Blo, nBlock, ldB, k0, sb + 32768, sb + 49152, tid);
        }
        CP_COMMIT();
        CP_WAIT1();
        __syncthreads();

        const uint32_t st = sbase + (ch & 1) * STAGE_BYTES;
        #pragma unroll
        for (int ks = 0; ks < 4; ks++) {
            uint32_t aH[4][4], aL[4][4];
            #pragma unroll
            for (int mi = 0; mi < 4; mi++) {
                uint32_t sw = SWZ128((uint32_t)((aRow + mi * 16) * 128 + ks * 32 + aKb));
                LDSM_X4(aH[mi][0], aH[mi][1], aH[mi][2], aH[mi][3], st + 0 + sw);
                LDSM_X4(aL[mi][0], aL[mi][1], aL[mi][2], aL[mi][3], st + 16384 + sw);
            }
            #pragma unroll
            for (int ni = 0; ni < 4; ni++) {
                uint32_t sw = SWZ128((uint32_t)((bRow + ni * 8) * 128 + ks * 32 + bKb));
                uint32_t bH0, bH1, bL0, bL1;
                LDSM_X2(bH0, bH1, st + 32768 + sw);
                LDSM_X2(bL0, bL1, st + 49152 + sw);
                #pragma unroll
                for (int mi = 0; mi < 4; mi++) {
                    mma16816(acc[mi][ni], aH[mi][0], aH[mi][1], aH[mi][2], aH[mi][3], bH0, bH1);
                    mma16816(acc[mi][ni], aH[mi][0], aH[mi][1], aH[mi][2], aH[mi][3], bL0, bL1);
                    mma16816(acc[mi][ni], aL[mi][0], aL[mi][1], aL[mi][2], aL[mi][3], bH0, bH1);
                }
            }
        }
        __syncthreads();
    }

    // ---- epilogue ----
    const int mLane = lane >> 2;
    const int nLane = (lane & 3) * 2;
    #pragma unroll
    for (int mi = 0; mi < 4; mi++) {
        const int m0 = mBlock + mWarp + mi * 16 + mLane;
        float br0 = 0.f, br1 = 0.f;
        if (BIAS_MODE == 1) { br0 = bias[m0]; br1 = bias[m0 + 8]; }
        #pragma unroll
        for (int ni = 0; ni < 4; ni++) {
            const int n = nBlock + nWarp + ni * 8 + nLane;
            float c0 = acc[mi][ni][0], c1 = acc[mi][ni][1];
            float c2 = acc[mi][ni][2], c3 = acc[mi][ni][3];
            if (BIAS_MODE == 1) { c0 += br0; c1 += br0; c2 += br1; c3 += br1; }
            if (BIAS_MODE == 2) {
                float bx = bias[n], by = bias[n + 1];
                c0 += bx; c1 += by; c2 += bx; c3 += by;
            }
            if (OUT_BF16) {
                __nv_bfloat16 h0, h1, h2, h3, l0, l1, l2, l3;
                split2(c0, h0, l0); split2(c1, h1, l1);
                split2(c2, h2, l2); split2(c3, h3, l3);
                *(__nv_bfloat162*)&Chi[coff + (long)m0 * ldC + n]       = __nv_bfloat162(h0, h1);
                *(__nv_bfloat162*)&Clo[coff + (long)m0 * ldC + n]       = __nv_bfloat162(l0, l1);
                *(__nv_bfloat162*)&Chi[coff + (long)(m0 + 8) * ldC + n] = __nv_bfloat162(h2, h3);
                *(__nv_bfloat162*)&Clo[coff + (long)(m0 + 8) * ldC + n] = __nv_bfloat162(l2, l3);
            } else {
                float2 v0 = {c0, c1}, v1 = {c2, c3};
                *(float2*)&Cf[coff + (long)m0 * ldC + n]       = v0;
                *(float2*)&Cf[coff + (long)(m0 + 8) * ldC + n] = v1;
            }
        }
    }
}

// ---------------- x transpose + hi/lo convert ----------------------------------
// x [b][c][n] -> xT hi/lo [b][n][c]
__global__ __launch_bounds__(256) void transpose_x(const float* __restrict__ x) {
    __shared__ float t[32][33];
    const int b = blockIdx.z;
    const int n0 = blockIdx.x * 32, c0 = blockIdx.y * 32;
    const int tx = threadIdx.x, ty = threadIdx.y;
    #pragma unroll
    for (int i = ty; i < 32; i += 8)
        t[i][tx] = x[((long)b * CC + c0 + i) * NN + n0 + tx];
    __syncthreads();
    #pragma unroll
    for (int i = ty; i < 32; i += 8) {
        float v = t[tx][i];   // x[c0+tx][n0+i]
        __nv_bfloat16 h, l;
        split2(v, h, l);
        const long o = ((long)b * NN + n0 + i) * CC + c0 + tx;
        g_xT_hi[o] = h;
        g_xT_lo[o] = l;
    }
}

// ---------------- weight convert (wcat, Ww, bias384) ---------------------------
__global__ __launch_bounds__(256) void convert_w(
    const float* __restrict__ tw, const float* __restrict__ pw, const float* __restrict__ gw,
    const float* __restrict__ tb, const float* __restrict__ pb, const float* __restrict__ gb,
    const float* __restrict__ Ww)
{
    const int i = blockIdx.x * 256 + threadIdx.x;
    const int TOT1 = 384 * CC;
    const int TOT2 = TOT1 + CC * CI;
    if (i < TOT1) {
        int o = i / CC, c = i % CC;
        float v = (o < 128) ? tw[o * CC + c] : (o < 256) ? pw[(o - 128) * CC + c] : gw[(o - 256) * CC + c];
        __nv_bfloat16 h, l; split2(v, h, l);
        g_w_hi[i] = h; g_w_lo[i] = l;
    } else if (i < TOT2) {
        float v = Ww[i - TOT1];
        __nv_bfloat16 h, l; split2(v, h, l);
        g_w_hi[i] = h; g_w_lo[i] = l;
    }
    if (i < 384)
        g_bias384[i] = (i < 128) ? tb[i] : (i < 256) ? pb[i - 128] : gb[i - 256];
}

// ---------------- 2x2 maxpool (phi/g from o3, hi/lo in, hi/lo out) -------------
__global__ __launch_bounds__(256) void pool_kernel() {
    const int i = blockIdx.x * 256 + threadIdx.x;   // over BB*MM*CI, ci fastest
    if (i >= BB * MM * CI) return;
    const int ci = i & (CI - 1);
    const int m  = (i >> 7) & (MM - 1);
    const int b  = i >> 17;
    const int hp = m >> 5, wp = m & 31;
    const int n0 = hp * 128 + wp * 2;
    const long rb = (long)b * NN;

    #pragma unroll
    for (int which = 0; which < 2; which++) {
        const int col = (which == 0 ? 128 : 256) + ci;
        float v00 = __bfloat162float(g_o3_hi[(rb + n0)      * 384 + col]) + __bfloat162float(g_o3_lo[(rb + n0)      * 384 + col]);
        float v01 = __bfloat162float(g_o3_hi[(rb + n0 + 1)  * 384 + col]) + __bfloat162float(g_o3_lo[(rb + n0 + 1)  * 384 + col]);
        float v10 = __bfloat162float(g_o3_hi[(rb + n0 + 64) * 384 + col]) + __bfloat162float(g_o3_lo[(rb + n0 + 64) * 384 + col]);
        float v11 = __bfloat162float(g_o3_hi[(rb + n0 + 65) * 384 + col]) + __bfloat162float(g_o3_lo[(rb + n0 + 65) * 384 + col]);
        float mx = fmaxf(fmaxf(v00, v01), fmaxf(v10, v11));
        __nv_bfloat16 h, l; split2(mx, h, l);
        if (which == 0) {
            const long o = ((long)b * MM + m) * CI + ci;
            g_phi_hi[o] = h; g_phi_lo[o] = l;
        } else {
            const long o = ((long)b * CI + ci) * MM + m;
            g_gT_hi[o] = h; g_gT_lo[o] = l;
        }
    }
}

// ---------------- row softmax over M=1024, outputs bf16 hi/lo ------------------
__global__ __launch_bounds__(256) void softmax_kernel() {
    const long roff = (long)blockIdx.x * MM;
    const float* row = g_f + roff;
    const int t = threadIdx.x;
    float4 v = ((const float4*)row)[t];

    float mx = fmaxf(fmaxf(v.x, v.y), fmaxf(v.z, v.w));
    #pragma unroll
    for (int o = 16; o; o >>= 1) mx = fmaxf(mx, __shfl_xor_sync(0xffffffffu, mx, o));
    __shared__ float smv[8];
    const int w = t >> 5, l = t & 31;
    if (l == 0) smv[w] = mx;
    __syncthreads();
    mx = smv[0];
    #pragma unroll
    for (int i = 1; i < 8; i++) mx = fmaxf(mx, smv[i]);
    __syncthreads();

    v.x = __expf(v.x - mx); v.y = __expf(v.y - mx);
    v.z = __expf(v.z - mx); v.w = __expf(v.w - mx);
    float s = v.x + v.y + v.z + v.w;
    #pragma unroll
    for (int o = 16; o; o >>= 1) s += __shfl_xor_sync(0xffffffffu, s, o);
    if (l == 0) smv[w] = s;
    __syncthreads();
    s = 0.f;
    #pragma unroll
    for (int i = 0; i < 8; i++) s += smv[i];
    const float inv = 1.f / s;
    v.x *= inv; v.y *= inv; v.z *= inv; v.w *= inv;

    __nv_bfloat16 h0, h1, h2, h3, l0, l1, l2, l3;
    split2(v.x, h0, l0); split2(v.y, h1, l1);
    split2(v.z, h2, l2); split2(v.w, h3, l3);
    *(__nv_bfloat162*)&g_f_hi[roff + 4 * t]     = __nv_bfloat162(h0, h1);
    *(__nv_bfloat162*)&g_f_hi[roff + 4 * t + 2] = __nv_bfloat162(h2, h3);
    *(__nv_bfloat162*)&g_f_lo[roff + 4 * t]     = __nv_bfloat162(l0, l1);
    *(__nv_bfloat162*)&g_f_lo[roff + 4 * t + 2] = __nv_bfloat162(l2, l3);
}

// ---------------- BN statistics (deterministic tree reduce) --------------------
__global__ __launch_bounds__(256) void bn_stats_kernel(const float* __restrict__ gamma,
                                                       const float* __restrict__ beta) {
    const int c = blockIdx.x;
    const int t = threadIdx.x;
    double s = 0.0, sq = 0.0;
    for (int i = t; i < BB * NN; i += 256) {
        const int b = i >> 12;
        const int n = i & (NN - 1);
        const float v = g_wy[(((long)b * CC + c) << 12) + n];
        s += (double)v;
        sq += (double)v * (double)v;
    }
    __shared__ double ss[256], sz[256];
    ss[t] = s; sz[t] = sq;
    __syncthreads();
    for (int st = 128; st; st >>= 1) {
        if (t < st) { ss[t] += ss[t + st]; sz[t] += sz[t + st]; }
        __syncthreads();
    }
    if (t == 0) {
        const double cnt = 1.0 / (double)(BB * NN);
        const double mean = ss[0] * cnt;
        const double var  = sz[0] * cnt - mean * mean;
        const double inv  = 1.0 / sqrt(var + 1e-5);
        const float sc = gamma[c] * (float)inv;
        g_scale[c] = sc;
        g_shift[c] = beta[c] - (float)mean * sc;
    }
}

// ---------------- apply BN + residual ------------------------------------------
__global__ __launch_bounds__(256) void final_kernel(const float* __restrict__ x,
                                                    float* __restrict__ out) {
    const long i = (long)blockIdx.x * 256 + threadIdx.x;
    const long e = i << 2;
    const int c = (int)((e >> 12) & (CC - 1));
    const float sc = g_scale[c], sh = g_shift[c];
    float4 wy = ((const float4*)g_wy)[i];
    float4 xv = ((const float4*)x)[i];
    float4 o;
    o.x = fmaf(wy.x, sc, sh) + xv.x;
    o.y = fmaf(wy.y, sc, sh) + xv.y;
    o.z = fmaf(wy.z, sc, sh) + xv.z;
    o.w = fmaf(wy.w, sc, sh) + xv.w;
    ((float4*)out)[i] = o;
}

// ------------------------------------------------------------------------------
extern "C" void kernel_launch(void* const* d_in, const int* in_sizes, int n_in,
                              void* d_out, int out_size) {
    (void)in_sizes; (void)n_in; (void)out_size;
    const float* x     = (const float*)d_in[0];
    const float* tw    = (const float*)d_in[1];
    const float* tb    = (const float*)d_in[2];
    const float* pw    = (const float*)d_in[3];
    const float* pb    = (const float*)d_in[4];
    const float* gw    = (const float*)d_in[5];
    const float* gb    = (const float*)d_in[6];
    const float* Ww    = (const float*)d_in[7];
    const float* Wb    = (const float*)d_in[8];
    const float* gamma = (const float*)d_in[9];
    const float* beta  = (const float*)d_in[10];
    float* out = (float*)d_out;

    __nv_bfloat16 *xTh, *xTl, *wh, *wl, *o3h, *o3l, *phih, *phil, *gTh, *gTl, *fh, *fl, *yh, *yl;
    float *f, *wy, *bias384;
    cudaGetSymbolAddress((void**)&xTh, g_xT_hi);  cudaGetSymbolAddress((void**)&xTl, g_xT_lo);
    cudaGetSymbolAddress((void**)&wh,  g_w_hi);   cudaGetSymbolAddress((void**)&wl,  g_w_lo);
    cudaGetSymbolAddress((void**)&o3h, g_o3_hi);  cudaGetSymbolAddress((void**)&o3l, g_o3_lo);
    cudaGetSymbolAddress((void**)&phih, g_phi_hi); cudaGetSymbolAddress((void**)&phil, g_phi_lo);
    cudaGetSymbolAddress((void**)&gTh, g_gT_hi);  cudaGetSymbolAddress((void**)&gTl, g_gT_lo);
    cudaGetSymbolAddress((void**)&fh,  g_f_hi);   cudaGetSymbolAddress((void**)&fl,  g_f_lo);
    cudaGetSymbolAddress((void**)&yh,  g_y_hi);   cudaGetSymbolAddress((void**)&yl,  g_y_lo);
    cudaGetSymbolAddress((void**)&f,   g_f);
    cudaGetSymbolAddress((void**)&wy,  g_wy);
    cudaGetSymbolAddress((void**)&bias384, g_bias384);

    cudaFuncSetAttribute(gemm_bf16<2, true >, cudaFuncAttributeMaxDynamicSharedMemorySize, SMEM_GEMM_BYTES);
    cudaFuncSetAttribute(gemm_bf16<0, false>, cudaFuncAttributeMaxDynamicSharedMemorySize, SMEM_GEMM_BYTES);
    cudaFuncSetAttribute(gemm_bf16<0, true >, cudaFuncAttributeMaxDynamicSharedMemorySize, SMEM_GEMM_BYTES);
    cudaFuncSetAttribute(gemm_bf16<1, false>, cudaFuncAttributeMaxDynamicSharedMemorySize, SMEM_GEMM_BYTES);

    // P1: convert weights + biases
    convert_w<<<(384 * CC + CC * CI + 255) / 256, 256>>>(tw, pw, gw, tb, pb, gb, Ww);
    // P2: transpose + convert x -> xT [b][n][c]
    transpose_x<<<dim3(NN / 32, CC / 32, BB), dim3(32, 8)>>>(x);

    // K1: o3[b][n][o<384] = xT[n][c] . wcat[o][c]  (col bias), out bf16 hi/lo
    gemm_bf16<2, true><<<dim3(3, 32, BB), 256, SMEM_GEMM_BYTES>>>(
        xTh, xTl, wh, wl, bias384, nullptr, o3h, o3l,
        CC, CC, 384, CC, (long)NN * CC, 0, (long)NN * 384);

    // K2: maxpool -> phi [m][ci], gT [ci][m] (bf16 hi/lo)
    pool_kernel<<<(BB * MM * CI + 255) / 256, 256>>>();

    // K3a: f[n][m] = theta[n][ci] . phi[m][ci]   (theta = o3 cols 0..127)
    gemm_bf16<0, false><<<dim3(MM / 128, NN / 128, BB), 256, SMEM_GEMM_BYTES>>>(
        o3h, o3l, phih, phil, nullptr, f, nullptr, nullptr,
        384, CI, MM, CI, (long)NN * 384, (long)MM * CI, (long)NN * MM);

    // K3b: softmax rows -> f hi/lo
    softmax_kernel<<<BB * NN, 256>>>();

    // K3c: y[n][ci] = f[n][m] . gT[ci][m], out bf16 hi/lo
    gemm_bf16<0, true><<<dim3(CI / 128, NN / 128, BB), 256, SMEM_GEMM_BYTES>>>(
        fh, fl, gTh, gTl, nullptr, nullptr, yh, yl,
        MM, MM, CI, MM, (long)NN * MM, (long)CI * MM, (long)NN * CI);

    // K4: wy[c][n] = Ww[c][ci] . y[n][ci]  (row bias Wb), out fp32
    gemm_bf16<1, false><<<dim3(NN / 128, CC / 128, BB), 256, SMEM_GEMM_BYTES>>>(
        wh + 384 * CC, wl + 384 * CC, yh, yl, Wb, wy, nullptr, nullptr,
        CI, CI, NN, CI, 0, (long)NN * CI, (long)CC * NN);

    // K5: BN statistics per channel
    bn_stats_kernel<<<CC, 256>>>(gamma, beta);

    // K6: apply BN + residual
    final_kernel<<<(BB * CC * NN) / 4 / 256, 256>>>(x, out);
}

// round 6
// speedup vs baseline: 2.4846x; 1.1852x over previous
#include <cuda_runtime.h>
#include <cuda_bf16.h>
#include <math.h>
#include <stdint.h>

#define BB 8
#define CC 256
#define CI 128
#define NN 4096
#define MM 1024

// ---------------- device-global scratch (no allocation allowed) ---------------
__device__ __align__(16) __nv_bfloat16 g_xT_hi[(long)BB * NN * CC];
__device__ __align__(16) __nv_bfloat16 g_xT_lo[(long)BB * NN * CC];
__device__ __align__(16) __nv_bfloat16 g_w_hi[384 * CC + CC * CI];
__device__ __align__(16) __nv_bfloat16 g_w_lo[384 * CC + CC * CI];
__device__ float g_bias384[384];
__device__ __align__(16) __nv_bfloat16 g_o3_hi[(long)BB * NN * 384];
__device__ __align__(16) __nv_bfloat16 g_o3_lo[(long)BB * NN * 384];
__device__ __align__(16) __nv_bfloat16 g_phi_hi[(long)BB * MM * CI];
__device__ __align__(16) __nv_bfloat16 g_phi_lo[(long)BB * MM * CI];
__device__ __align__(16) __nv_bfloat16 g_gT_hi[(long)BB * CI * MM];
__device__ __align__(16) __nv_bfloat16 g_gT_lo[(long)BB * CI * MM];
__device__ __align__(16) __nv_bfloat16 g_y_hi[(long)BB * NN * CI];
__device__ __align__(16) __nv_bfloat16 g_y_lo[(long)BB * NN * CI];
__device__ float g_wy[(long)BB * CC * NN];
__device__ float g_scale[CC], g_shift[CC];

#define SWZ128(off) ((uint32_t)(off) ^ (((uint32_t)(off) >> 3) & 0x70))
#define SWZ256(off) ((uint32_t)(off) ^ (((uint32_t)(off) >> 4) & 0x70))

// ---------------- PTX wrappers ------------------------------------------------
__device__ __forceinline__ uint32_t smem_u32(const void* p) {
    uint32_t a;
    asm("{ .reg .u64 t; cvta.to.shared.u64 t, %1; cvt.u32.u64 %0, t; }" : "=r"(a) : "l"(p));
    return a;
}
#define LDSM_X4(r0, r1, r2, r3, addr) \
    asm volatile("ldmatrix.sync.aligned.m8n8.x4.shared.b16 {%0,%1,%2,%3}, [%4];" \
                 : "=r"(r0), "=r"(r1), "=r"(r2), "=r"(r3) : "r"(addr))
#define LDSM_X2(r0, r1, addr) \
    asm volatile("ldmatrix.sync.aligned.m8n8.x2.shared.b16 {%0,%1}, [%2];" \
                 : "=r"(r0), "=r"(r1) : "r"(addr))
__device__ __forceinline__ void mma16816(float* c, uint32_t a0, uint32_t a1, uint32_t a2, uint32_t a3,
                                         uint32_t b0, uint32_t b1) {
    asm volatile(
        "mma.sync.aligned.m16n8k16.row.col.f32.bf16.bf16.f32 "
        "{%0,%1,%2,%3}, {%4,%5,%6,%7}, {%8,%9}, {%0,%1,%2,%3};"
        : "+f"(c[0]), "+f"(c[1]), "+f"(c[2]), "+f"(c[3])
        : "r"(a0), "r"(a1), "r"(a2), "r"(a3), "r"(b0), "r"(b1));
}
__device__ __forceinline__ void cpa16(uint32_t dst, const void* src) {
    asm volatile("cp.async.cg.shared.global [%0], [%1], 16;" :: "r"(dst), "l"(src));
}
#define CP_COMMIT() asm volatile("cp.async.commit_group;")
#define CP_WAIT1()  asm volatile("cp.async.wait_group 1;")
#define CP_WAIT0()  asm volatile("cp.async.wait_group 0;")

__device__ __forceinline__ void split2(float v, __nv_bfloat16& h, __nv_bfloat16& l) {
    h = __float2bfloat16(v);
    l = __float2bfloat16(v - __bfloat162float(h));
}
__device__ __forceinline__ uint32_t pk2(float e, float o) {   // e -> low, o -> high
    __nv_bfloat162 v(__float2bfloat16(e), __float2bfloat16(o));
    return *(uint32_t*)&v;
}

// =====================  bf16 hi/lo pipelined tensor-core GEMM  ================
#define STAGE_BYTES 65536
#define SMEM_GEMM_BYTES (2 * STAGE_BYTES)

__device__ __forceinline__ void load_op(const __nv_bfloat16* hi, const __nv_bfloat16* lo,
                                        int rowBase, int ld, int k0,
                                        uint32_t smH, uint32_t smL, int tid) {
    #pragma unroll
    for (int it = 0; it < 4; it++) {
        int idx = it * 256 + tid;
        int r = idx >> 3, s = idx & 7;
        uint32_t sw = SWZ128(r * 128 + s * 16);
        cpa16(smH + sw, hi + (long)(rowBase + r) * ld + k0 + s * 8);
        cpa16(smL + sw, lo + (long)(rowBase + r) * ld + k0 + s * 8);
    }
}

template<int BIAS_MODE, bool OUT_BF16>
__global__ __launch_bounds__(256) void gemm_bf16(
    const __nv_bfloat16* __restrict__ Ahi, const __nv_bfloat16* __restrict__ Alo,
    const __nv_bfloat16* __restrict__ Bhi, const __nv_bfloat16* __restrict__ Blo,
    const float* __restrict__ bias,
    float* __restrict__ Cf, __nv_bfloat16* __restrict__ Chi, __nv_bfloat16* __restrict__ Clo,
    int ldA, int ldB, int ldC, int K,
    long sA, long sB, long sC)
{
    extern __shared__ __align__(1024) char sm[];
    const int bz = blockIdx.z;
    Ahi += (long)bz * sA; Alo += (long)bz * sA;
    Bhi += (long)bz * sB; Blo += (long)bz * sB;
    const long coff = (long)bz * sC;

    const int mBlock = blockIdx.y * 128;
    const int nBlock = blockIdx.x * 128;
    const int tid = threadIdx.x;
    const int wid = tid >> 5;
    const int lane = tid & 31;
    const uint32_t sbase = smem_u32(sm);

    const int mWarp = (wid >> 2) * 64;
    const int nWarp = (wid & 3) * 32;

    float acc[4][4][4];
    #pragma unroll
    for (int i = 0; i < 4; i++)
        #pragma unroll
        for (int j = 0; j < 4; j++)
            #pragma unroll
            for (int r = 0; r < 4; r++) acc[i][j][r] = 0.f;

    const int aRow = mWarp + (lane & 15);
    const int aKb  = (lane >> 4) << 4;
    const int bRow = nWarp + (lane & 7);
    const int bKb  = ((lane >> 3) & 1) << 4;

    const int nChunks = K >> 6;
    load_op(Ahi, Alo, mBlock, ldA, 0, sbase + 0,     sbase + 16384, tid);
    load_op(Bhi, Blo, nBlock, ldB, 0, sbase + 32768, sbase + 49152, tid);
    CP_COMMIT();

    for (int ch = 0; ch < nChunks; ch++) {
        if (ch + 1 < nChunks) {
            const uint32_t sb = sbase + ((ch + 1) & 1) * STAGE_BYTES;
            const int k0 = (ch + 1) << 6;
            load_op(Ahi, Alo, mBlock, ldA, k0, sb + 0,     sb + 16384, tid);
            load_op(Bhi, Blo, nBlock, ldB, k0, sb + 32768, sb + 49152, tid);
        }
        CP_COMMIT();
        CP_WAIT1();
        __syncthreads();

        const uint32_t st = sbase + (ch & 1) * STAGE_BYTES;
        #pragma unroll
        for (int ks = 0; ks < 4; ks++) {
            uint32_t aH[4][4], aL[4][4];
            #pragma unroll
            for (int mi = 0; mi < 4; mi++) {
                uint32_t sw = SWZ128((aRow + mi * 16) * 128 + ks * 32 + aKb);
                LDSM_X4(aH[mi][0], aH[mi][1], aH[mi][2], aH[mi][3], st + 0 + sw);
                LDSM_X4(aL[mi][0], aL[mi][1], aL[mi][2], aL[mi][3], st + 16384 + sw);
            }
            #pragma unroll
            for (int ni = 0; ni < 4; ni++) {
                uint32_t sw = SWZ128((bRow + ni * 8) * 128 + ks * 32 + bKb);
                uint32_t bH0, bH1, bL0, bL1;
                LDSM_X2(bH0, bH1, st + 32768 + sw);
                LDSM_X2(bL0, bL1, st + 49152 + sw);
                #pragma unroll
                for (int mi = 0; mi < 4; mi++) {
                    mma16816(acc[mi][ni], aH[mi][0], aH[mi][1], aH[mi][2], aH[mi][3], bH0, bH1);
                    mma16816(acc[mi][ni], aH[mi][0], aH[mi][1], aH[mi][2], aH[mi][3], bL0, bL1);
                    mma16816(acc[mi][ni], aL[mi][0], aL[mi][1], aL[mi][2], aL[mi][3], bH0, bH1);
                }
            }
        }
        __syncthreads();
    }

    const int mLane = lane >> 2;
    const int nLane = (lane & 3) * 2;
    #pragma unroll
    for (int mi = 0; mi < 4; mi++) {
        const int m0 = mBlock + mWarp + mi * 16 + mLane;
        float br0 = 0.f, br1 = 0.f;
        if (BIAS_MODE == 1) { br0 = bias[m0]; br1 = bias[m0 + 8]; }
        #pragma unroll
        for (int ni = 0; ni < 4; ni++) {
            const int n = nBlock + nWarp + ni * 8 + nLane;
            float c0 = acc[mi][ni][0], c1 = acc[mi][ni][1];
            float c2 = acc[mi][ni][2], c3 = acc[mi][ni][3];
            if (BIAS_MODE == 1) { c0 += br0; c1 += br0; c2 += br1; c3 += br1; }
            if (BIAS_MODE == 2) {
                float bx = bias[n], by = bias[n + 1];
                c0 += bx; c1 += by; c2 += bx; c3 += by;
            }
            if (OUT_BF16) {
                __nv_bfloat16 h0, h1, h2, h3, l0, l1, l2, l3;
                split2(c0, h0, l0); split2(c1, h1, l1);
                split2(c2, h2, l2); split2(c3, h3, l3);
                *(__nv_bfloat162*)&Chi[coff + (long)m0 * ldC + n]       = __nv_bfloat162(h0, h1);
                *(__nv_bfloat162*)&Clo[coff + (long)m0 * ldC + n]       = __nv_bfloat162(l0, l1);
                *(__nv_bfloat162*)&Chi[coff + (long)(m0 + 8) * ldC + n] = __nv_bfloat162(h2, h3);
                *(__nv_bfloat162*)&Clo[coff + (long)(m0 + 8) * ldC + n] = __nv_bfloat162(l2, l3);
            } else {
                float2 v0 = {c0, c1}, v1 = {c2, c3};
                *(float2*)&Cf[coff + (long)m0 * ldC + n]       = v0;
                *(float2*)&Cf[coff + (long)(m0 + 8) * ldC + n] = v1;
            }
        }
    }
}

// =====================  fused attention (theta.phi^T -> softmax -> .g)  =======
// Grid (NN/128, BB). CTA: 128 theta rows, loop 16 m-chunks of 64 (double-buffered).
// SMEM: theta hi/lo [128][128ci] (SWZ256, 2x32KB) + 2 buffers of
//       { phi hi/lo [64][128ci] SWZ256 (2x16KB), gT hi/lo [128ci][64m] SWZ128 (2x16KB) }.
#define ATT_SMEM (65536 + 2 * 65536)

__device__ __forceinline__ void att_load_chunk(int b, int m0, uint32_t buf, int tid) {
    const __nv_bfloat16* ph = g_phi_hi + ((long)b * MM + m0) * CI;
    const __nv_bfloat16* pl = g_phi_lo + ((long)b * MM + m0) * CI;
    #pragma unroll
    for (int it = 0; it < 4; it++) {
        int idx = it * 256 + tid;       // 1024: r(64) x s(16)
        int r = idx >> 4, s = idx & 15;
        uint32_t sw = SWZ256(r * 256 + s * 16);
        cpa16(buf + 0 + sw,     ph + (long)r * CI + s * 8);
        cpa16(buf + 16384 + sw, pl + (long)r * CI + s * 8);
    }
    const __nv_bfloat16* gh = g_gT_hi + (long)b * CI * MM + m0;
    const __nv_bfloat16* gl = g_gT_lo + (long)b * CI * MM + m0;
    #pragma unroll
    for (int it = 0; it < 4; it++) {
        int idx = it * 256 + tid;       // 1024: r(128) x s(8)
        int r = idx >> 3, s = idx & 7;
        uint32_t sw = SWZ128(r * 128 + s * 16);
        cpa16(buf + 32768 + sw, gh + (long)r * MM + s * 8);
        cpa16(buf + 49152 + sw, gl + (long)r * MM + s * 8);
    }
}

__global__ __launch_bounds__(256, 1) void attn_kernel() {
    extern __shared__ __align__(1024) char sm[];
    const int b = blockIdx.y;
    const int nBlock = blockIdx.x * 128;
    const int tid = threadIdx.x;
    const int wid = tid >> 5;
    const int lane = tid & 31;
    const uint32_t sbase = smem_u32(sm);
    const uint32_t TH = 0, TL = 32768, BUF0 = 65536;

    // ---- load theta tile (persistent) ----
    {
        const __nv_bfloat16* th = g_o3_hi + ((long)b * NN + nBlock) * 384;
        const __nv_bfloat16* tl = g_o3_lo + ((long)b * NN + nBlock) * 384;
        #pragma unroll
        for (int it = 0; it < 8; it++) {
            int idx = it * 256 + tid;   // 2048: r(128) x s(16)
            int r = idx >> 4, s = idx & 15;
            uint32_t sw = SWZ256(r * 256 + s * 16);
            cpa16(sbase + TH + sw, th + (long)r * 384 + s * 8);
            cpa16(sbase + TL + sw, tl + (long)r * 384 + s * 8);
        }
    }
    att_load_chunk(b, 0, sbase + BUF0, tid);
    CP_COMMIT();

    float yacc[16][4];
    #pragma unroll
    for (int t = 0; t < 16; t++)
        #pragma unroll
        for (int r = 0; r < 4; r++) yacc[t][r] = 0.f;
    float rm0 = -1e30f, rm1 = -1e30f, rl0 = 0.f, rl1 = 0.f;

    const int aRowOff = wid * 16 + (lane & 15);
    const uint32_t aKb = (lane >> 4) << 4;
    const int bR = (lane & 7) + ((lane >> 4) & 1) * 8;   // pair-row pattern
    const uint32_t bKb = ((lane >> 3) & 1) << 4;

    for (int ch = 0; ch < 16; ch++) {
        if (ch < 15) {
            att_load_chunk(b, (ch + 1) * 64, sbase + BUF0 + ((ch + 1) & 1) * 65536, tid);
            CP_COMMIT();
            CP_WAIT1();
        } else {
            CP_WAIT0();
        }
        __syncthreads();
        const uint32_t bs = sbase + BUF0 + (ch & 1) * 65536;

        // ---- S = theta . phi^T  (128 x 64 per CTA-chunk; warp: 16 x 64) ----
        float sacc[8][4];
        #pragma unroll
        for (int j = 0; j < 8; j++)
            #pragma unroll
            for (int r = 0; r < 4; r++) sacc[j][r] = 0.f;

        #pragma unroll
        for (int ks = 0; ks < 8; ks++) {
            uint32_t aH0, aH1, aH2, aH3, aL0, aL1, aL2, aL3;
            uint32_t swA = SWZ256(aRowOff * 256 + ks * 32 + aKb);
            LDSM_X4(aH0, aH1, aH2, aH3, sbase + TH + swA);
            LDSM_X4(aL0, aL1, aL2, aL3, sbase + TL + swA);
            #pragma unroll
            for (int jp = 0; jp < 4; jp++) {
                uint32_t swB = SWZ256((jp * 16 + bR) * 256 + ks * 32 + bKb);
                uint32_t bh0, bh1, bh2, bh3, bl0, bl1, bl2, bl3;
                LDSM_X4(bh0, bh1, bh2, bh3, bs + 0 + swB);
                LDSM_X4(bl0, bl1, bl2, bl3, bs + 16384 + swB);
                mma16816(sacc[2 * jp],     aH0, aH1, aH2, aH3, bh0, bh1);
                mma16816(sacc[2 * jp],     aH0, aH1, aH2, aH3, bl0, bl1);
                mma16816(sacc[2 * jp],     aL0, aL1, aL2, aL3, bh0, bh1);
                mma16816(sacc[2 * jp + 1], aH0, aH1, aH2, aH3, bh2, bh3);
                mma16816(sacc[2 * jp + 1], aH0, aH1, aH2, aH3, bl2, bl3);
                mma16816(sacc[2 * jp + 1], aL0, aL1, aL2, aL3, bh2, bh3);
            }
        }

        // ---- online softmax ----
        float cm0 = -1e30f, cm1 = -1e30f;
        #pragma unroll
        for (int j = 0; j < 8; j++) {
            cm0 = fmaxf(cm0, fmaxf(sacc[j][0], sacc[j][1]));
            cm1 = fmaxf(cm1, fmaxf(sacc[j][2], sacc[j][3]));
        }
        cm0 = fmaxf(cm0, __shfl_xor_sync(0xffffffffu, cm0, 1));
        cm0 = fmaxf(cm0, __shfl_xor_sync(0xffffffffu, cm0, 2));
        cm1 = fmaxf(cm1, __shfl_xor_sync(0xffffffffu, cm1, 1));
        cm1 = fmaxf(cm1, __shfl_xor_sync(0xffffffffu, cm1, 2));
        const float nm0 = fmaxf(rm0, cm0);
        const float nm1 = fmaxf(rm1, cm1);
        const float al0 = __expf(rm0 - nm0);
        const float al1 = __expf(rm1 - nm1);

        uint32_t pH[8][2], pL[8][2];
        float ps0 = 0.f, ps1 = 0.f;
        #pragma unroll
        for (int j = 0; j < 8; j++) {
            float e0 = __expf(sacc[j][0] - nm0);
            float e1 = __expf(sacc[j][1] - nm0);
            float e2 = __expf(sacc[j][2] - nm1);
            float e3 = __expf(sacc[j][3] - nm1);
            ps0 += e0 + e1; ps1 += e2 + e3;
            float h0 = __bfloat162float(__float2bfloat16(e0));
            float h1 = __bfloat162float(__float2bfloat16(e1));
            float h2 = __bfloat162float(__float2bfloat16(e2));
            float h3 = __bfloat162float(__float2bfloat16(e3));
            pH[j][0] = pk2(e0, e1);
            pH[j][1] = pk2(e2, e3);
            pL[j][0] = pk2(e0 - h0, e1 - h1);
            pL[j][1] = pk2(e2 - h2, e3 - h3);
        }
        ps0 += __shfl_xor_sync(0xffffffffu, ps0, 1);
        ps0 += __shfl_xor_sync(0xffffffffu, ps0, 2);
        ps1 += __shfl_xor_sync(0xffffffffu, ps1, 1);
        ps1 += __shfl_xor_sync(0xffffffffu, ps1, 2);
        rl0 = rl0 * al0 + ps0;
        rl1 = rl1 * al1 + ps1;
        rm0 = nm0; rm1 = nm1;
        #pragma unroll
        for (int t = 0; t < 16; t++) {
            yacc[t][0] *= al0; yacc[t][1] *= al0;
            yacc[t][2] *= al1; yacc[t][3] *= al1;
        }

        // ---- y += P . g  (k = m chunk 64, out ci = 128) ----
        #pragma unroll
        for (int kk = 0; kk < 4; kk++) {
            const uint32_t ah0 = pH[2 * kk][0], ah1 = pH[2 * kk][1];
            const uint32_t ah2 = pH[2 * kk + 1][0], ah3 = pH[2 * kk + 1][1];
            const uint32_t al0r = pL[2 * kk][0], al1r = pL[2 * kk][1];
            const uint32_t al2r = pL[2 * kk + 1][0], al3r = pL[2 * kk + 1][1];
            #pragma unroll
            for (int t2 = 0; t2 < 8; t2++) {
                uint32_t swG = SWZ128((t2 * 16 + bR) * 128 + kk * 32 + bKb);
                uint32_t gh0, gh1, gh2, gh3, gl0, gl1, gl2, gl3;
                LDSM_X4(gh0, gh1, gh2, gh3, bs + 32768 + swG);
                LDSM_X4(gl0, gl1, gl2, gl3, bs + 49152 + swG);
                mma16816(yacc[2 * t2],     ah0, ah1, ah2, ah3, gh0, gh1);
                mma16816(yacc[2 * t2],     ah0, ah1, ah2, ah3, gl0, gl1);
                mma16816(yacc[2 * t2],     al0r, al1r, al2r, al3r, gh0, gh1);
                mma16816(yacc[2 * t2 + 1], ah0, ah1, ah2, ah3, gh2, gh3);
                mma16816(yacc[2 * t2 + 1], ah0, ah1, ah2, ah3, gl2, gl3);
                mma16816(yacc[2 * t2 + 1], al0r, al1r, al2r, al3r, gh2, gh3);
            }
        }
        __syncthreads();
    }

    // ---- epilogue: y /= l, write hi/lo ----
    const float inv0 = 1.f / rl0;
    const float inv1 = 1.f / rl1;
    const int n0 = nBlock + wid * 16 + (lane >> 2);
    const int cB = (lane & 3) * 2;
    #pragma unroll
    for (int t = 0; t < 16; t++) {
        const int ci = t * 8 + cB;
        float c0 = yacc[t][0] * inv0, c1 = yacc[t][1] * inv0;
        float c2 = yacc[t][2] * inv1, c3 = yacc[t][3] * inv1;
        __nv_bfloat16 h0, h1, h2, h3, l0, l1, l2, l3;
        split2(c0, h0, l0); split2(c1, h1, l1);
        split2(c2, h2, l2); split2(c3, h3, l3);
        const long o0 = ((long)b * NN + n0) * CI + ci;
        const long o1 = ((long)b * NN + n0 + 8) * CI + ci;
        *(__nv_bfloat162*)&g_y_hi[o0] = __nv_bfloat162(h0, h1);
        *(__nv_bfloat162*)&g_y_lo[o0] = __nv_bfloat162(l0, l1);
        *(__nv_bfloat162*)&g_y_hi[o1] = __nv_bfloat162(h2, h3);
        *(__nv_bfloat162*)&g_y_lo[o1] = __nv_bfloat162(l2, l3);
    }
}

// ---------------- x transpose + hi/lo convert ----------------------------------
__global__ __launch_bounds__(256) void transpose_x(const float* __restrict__ x) {
    __shared__ float t[32][33];
    const int b = blockIdx.z;
    const int n0 = blockIdx.x * 32, c0 = blockIdx.y * 32;
    const int tx = threadIdx.x, ty = threadIdx.y;
    #pragma unroll
    for (int i = ty; i < 32; i += 8)
        t[i][tx] = x[((long)b * CC + c0 + i) * NN + n0 + tx];
    __syncthreads();
    #pragma unroll
    for (int i = ty; i < 32; i += 8) {
        float v = t[tx][i];
        __nv_bfloat16 h, l;
        split2(v, h, l);
        const long o = ((long)b * NN + n0 + i) * CC + c0 + tx;
        g_xT_hi[o] = h;
        g_xT_lo[o] = l;
    }
}

// ---------------- weight convert ------------------------------------------------
__global__ __launch_bounds__(256) void convert_w(
    const float* __restrict__ tw, const float* __restrict__ pw, const float* __restrict__ gw,
    const float* __restrict__ tb, const float* __restrict__ pb, const float* __restrict__ gb,
    const float* __restrict__ Ww)
{
    const int i = blockIdx.x * 256 + threadIdx.x;
    const int TOT1 = 384 * CC;
    const int TOT2 = TOT1 + CC * CI;
    if (i < TOT1) {
        int o = i / CC, c = i % CC;
        float v = (o < 128) ? tw[o * CC + c] : (o < 256) ? pw[(o - 128) * CC + c] : gw[(o - 256) * CC + c];
        __nv_bfloat16 h, l; split2(v, h, l);
        g_w_hi[i] = h; g_w_lo[i] = l;
    } else if (i < TOT2) {
        float v = Ww[i - TOT1];
        __nv_bfloat16 h, l; split2(v, h, l);
        g_w_hi[i] = h; g_w_lo[i] = l;
    }
    if (i < 384)
        g_bias384[i] = (i < 128) ? tb[i] : (i < 256) ? pb[i - 128] : gb[i - 256];
}

// ---------------- 2x2 maxpool (vectorized 4-ci per thread) ----------------------
__device__ __forceinline__ void ld4bf(const __nv_bfloat16* p, float* out) {
    uint2 u = *(const uint2*)p;
    __nv_bfloat162 a = *(__nv_bfloat162*)&u.x;
    __nv_bfloat162 bq = *(__nv_bfloat162*)&u.y;
    out[0] = __bfloat162float(a.x); out[1] = __bfloat162float(a.y);
    out[2] = __bfloat162float(bq.x); out[3] = __bfloat162float(bq.y);
}

__global__ __launch_bounds__(256) void pool_kernel() {
    const int i = blockIdx.x * 256 + threadIdx.x;   // BB*MM*32
    if (i >= BB * MM * 32) return;
    const int c4 = (i & 31) << 2;
    const int m  = (i >> 5) & (MM - 1);
    const int b  = i >> 15;
    const int hp = m >> 5, wp = m & 31;
    const int n0 = hp * 128 + wp * 2;
    const long rb = (long)b * NN;

    #pragma unroll
    for (int which = 0; which < 2; which++) {
        const int col = (which == 0 ? 128 : 256) + c4;
        float mx[4] = {-1e30f, -1e30f, -1e30f, -1e30f};
        #pragma unroll
        for (int rr = 0; rr < 4; rr++) {
            const int n = n0 + (rr & 1) + (rr >> 1) * 64;
            const long base = (rb + n) * 384 + col;
            float vh[4], vl[4];
            ld4bf(&g_o3_hi[base], vh);
            ld4bf(&g_o3_lo[base], vl);
            #pragma unroll
            for (int e = 0; e < 4; e++) mx[e] = fmaxf(mx[e], vh[e] + vl[e]);
        }
        __nv_bfloat16 h[4], l[4];
        #pragma unroll
        for (int e = 0; e < 4; e++) split2(mx[e], h[e], l[e]);
        if (which == 0) {
            const long o = ((long)b * MM + m) * CI + c4;
            *(__nv_bfloat162*)&g_phi_hi[o]     = __nv_bfloat162(h[0], h[1]);
            *(__nv_bfloat162*)&g_phi_hi[o + 2] = __nv_bfloat162(h[2], h[3]);
            *(__nv_bfloat162*)&g_phi_lo[o]     = __nv_bfloat162(l[0], l[1]);
            *(__nv_bfloat162*)&g_phi_lo[o + 2] = __nv_bfloat162(l[2], l[3]);
        } else {
            #pragma unroll
            for (int e = 0; e < 4; e++) {
                const long o = ((long)b * CI + c4 + e) * MM + m;
                g_gT_hi[o] = h[e];
                g_gT_lo[o] = l[e];
            }
        }
    }
}

// ---------------- BN statistics (deterministic tree reduce, float4) -------------
__global__ __launch_bounds__(256) void bn_stats_kernel(const float* __restrict__ gamma,
                                                       const float* __restrict__ beta) {
    const int c = blockIdx.x;
    const int t = threadIdx.x;
    double s = 0.0, sq = 0.0;
    for (int i = t; i < BB * NN / 4; i += 256) {
        const int b = i >> 10;
        const int n4 = (i & 1023) << 2;
        float4 v = *(const float4*)&g_wy[(((long)b * CC + c) << 12) + n4];
        s += (double)v.x + (double)v.y + (double)v.z + (double)v.w;
        sq += (double)v.x * v.x + (double)v.y * v.y + (double)v.z * v.z + (double)v.w * v.w;
    }
    __shared__ double ss[256], sz[256];
    ss[t] = s; sz[t] = sq;
    __syncthreads();
    for (int st = 128; st; st >>= 1) {
        if (t < st) { ss[t] += ss[t + st]; sz[t] += sz[t + st]; }
        __syncthreads();
    }
    if (t == 0) {
        const double cnt = 1.0 / (double)(BB * NN);
        const double mean = ss[0] * cnt;
        const double var  = sz[0] * cnt - mean * mean;
        const double inv  = 1.0 / sqrt(var + 1e-5);
        const float sc = gamma[c] * (float)inv;
        g_scale[c] = sc;
        g_shift[c] = beta[c] - (float)mean * sc;
    }
}

// ---------------- apply BN + residual ------------------------------------------
__global__ __launch_bounds__(256) void final_kernel(const float* __restrict__ x,
                                                    float* __restrict__ out) {
    const long i = (long)blockIdx.x * 256 + threadIdx.x;
    const long e = i << 2;
    const int c = (int)((e >> 12) & (CC - 1));
    const float sc = g_scale[c], sh = g_shift[c];
    float4 wy = ((const float4*)g_wy)[i];
    float4 xv = ((const float4*)x)[i];
    float4 o;
    o.x = fmaf(wy.x, sc, sh) + xv.x;
    o.y = fmaf(wy.y, sc, sh) + xv.y;
    o.z = fmaf(wy.z, sc, sh) + xv.z;
    o.w = fmaf(wy.w, sc, sh) + xv.w;
    ((float4*)out)[i] = o;
}

// ------------------------------------------------------------------------------
extern "C" void kernel_launch(void* const* d_in, const int* in_sizes, int n_in,
                              void* d_out, int out_size) {
    (void)in_sizes; (void)n_in; (void)out_size;
    const float* x     = (const float*)d_in[0];
    const float* tw    = (const float*)d_in[1];
    const float* tb    = (const float*)d_in[2];
    const float* pw    = (const float*)d_in[3];
    const float* pb    = (const float*)d_in[4];
    const float* gw    = (const float*)d_in[5];
    const float* gb    = (const float*)d_in[6];
    const float* Ww    = (const float*)d_in[7];
    const float* Wb    = (const float*)d_in[8];
    const float* gamma = (const float*)d_in[9];
    const float* beta  = (const float*)d_in[10];
    float* out = (float*)d_out;

    __nv_bfloat16 *xTh, *xTl, *wh, *wl, *o3h, *o3l, *yh, *yl;
    float *wy, *bias384;
    cudaGetSymbolAddress((void**)&xTh, g_xT_hi);  cudaGetSymbolAddress((void**)&xTl, g_xT_lo);
    cudaGetSymbolAddress((void**)&wh,  g_w_hi);   cudaGetSymbolAddress((void**)&wl,  g_w_lo);
    cudaGetSymbolAddress((void**)&o3h, g_o3_hi);  cudaGetSymbolAddress((void**)&o3l, g_o3_lo);
    cudaGetSymbolAddress((void**)&yh,  g_y_hi);   cudaGetSymbolAddress((void**)&yl,  g_y_lo);
    cudaGetSymbolAddress((void**)&wy,  g_wy);
    cudaGetSymbolAddress((void**)&bias384, g_bias384);

    cudaFuncSetAttribute(gemm_bf16<2, true >, cudaFuncAttributeMaxDynamicSharedMemorySize, SMEM_GEMM_BYTES);
    cudaFuncSetAttribute(gemm_bf16<1, false>, cudaFuncAttributeMaxDynamicSharedMemorySize, SMEM_GEMM_BYTES);
    cudaFuncSetAttribute(attn_kernel, cudaFuncAttributeMaxDynamicSharedMemorySize, ATT_SMEM);

    // P1: convert weights + biases
    convert_w<<<(384 * CC + CC * CI + 255) / 256, 256>>>(tw, pw, gw, tb, pb, gb, Ww);
    // P2: transpose + convert x -> xT [b][n][c]
    transpose_x<<<dim3(NN / 32, CC / 32, BB), dim3(32, 8)>>>(x);

    // K1: o3[b][n][o<384] = xT[n][c] . wcat[o][c]  (col bias), out bf16 hi/lo
    gemm_bf16<2, true><<<dim3(3, 32, BB), 256, SMEM_GEMM_BYTES>>>(
        xTh, xTl, wh, wl, bias384, nullptr, o3h, o3l,
        CC, CC, 384, CC, (long)NN * CC, 0, (long)NN * 384);

    // K2: maxpool -> phi [m][ci], gT [ci][m] (bf16 hi/lo)
    pool_kernel<<<(BB * MM * 32 + 255) / 256, 256>>>();

    // K3: fused theta.phi^T -> softmax -> .g  ==> y [b][n][ci] bf16 hi/lo
    attn_kernel<<<dim3(NN / 128, BB), 256, ATT_SMEM>>>();

    // K4: wy[c][n] = Ww[c][ci] . y[n][ci]  (row bias Wb), out fp32
    gemm_bf16<1, false><<<dim3(NN / 128, CC / 128, BB), 256, SMEM_GEMM_BYTES>>>(
        wh + 384 * CC, wl + 384 * CC, yh, yl, Wb, wy, nullptr, nullptr,
        CI, CI, NN, CI, 0, (long)NN * CI, (long)CC * NN);

    // K5: BN statistics per channel
    bn_stats_kernel<<<CC, 256>>>(gamma, beta);

    // K6: apply BN + residual
    final_kernel<<<(BB * CC * NN) / 4 / 256, 256>>>(x, out);
}

// round 9
// speedup vs baseline: 3.0876x; 1.2427x over previous
#include <cuda_runtime.h>
#include <cuda_bf16.h>
#include <math.h>
#include <stdint.h>

#define BB 8
#define CC 256
#define CI 128
#define NN 4096
#define MM 1024

// ---------------- device-global scratch (no allocation allowed) ---------------
__device__ __align__(16) __nv_bfloat16 g_xT_hi[(long)BB * NN * CC];
__device__ __align__(16) __nv_bfloat16 g_xT_lo[(long)BB * NN * CC];
__device__ __align__(16) __nv_bfloat16 g_w_hi[384 * CC + CC * CI];
__device__ __align__(16) __nv_bfloat16 g_w_lo[384 * CC + CC * CI];
__device__ float g_bias384[384];
__device__ __align__(16) __nv_bfloat16 g_o3_hi[(long)BB * NN * 384];
__device__ __align__(16) __nv_bfloat16 g_o3_lo[(long)BB * NN * 384];
__device__ __align__(16) __nv_bfloat16 g_phi_hi[(long)BB * MM * CI];  // [b][m][ci]
__device__ __align__(16) __nv_bfloat16 g_phi_lo[(long)BB * MM * CI];
__device__ __align__(16) __nv_bfloat16 g_gm_hi[(long)BB * MM * CI];   // [b][m][ci]
__device__ __align__(16) __nv_bfloat16 g_gm_lo[(long)BB * MM * CI];
__device__ __align__(16) __nv_bfloat16 g_y_hi[(long)BB * NN * CI];
__device__ __align__(16) __nv_bfloat16 g_y_lo[(long)BB * NN * CI];
__device__ float g_wy[(long)BB * CC * NN];
__device__ float g_part_s[CC * 1024];
__device__ float g_part_q[CC * 1024];
__device__ float g_scale[CC], g_shift[CC];

#define SWZ128(off) ((uint32_t)(off) ^ (((uint32_t)(off) >> 3) & 0x70))
#define SWZ256(off) ((uint32_t)(off) ^ (((uint32_t)(off) >> 4) & 0x70))

// ---------------- PTX wrappers ------------------------------------------------
__device__ __forceinline__ uint32_t smem_u32(const void* p) {
    uint32_t a;
    asm("{ .reg .u64 t; cvta.to.shared.u64 t, %1; cvt.u32.u64 %0, t; }" : "=r"(a) : "l"(p));
    return a;
}
#define LDSM_X4(r0, r1, r2, r3, addr) \
    asm volatile("ldmatrix.sync.aligned.m8n8.x4.shared.b16 {%0,%1,%2,%3}, [%4];" \
                 : "=r"(r0), "=r"(r1), "=r"(r2), "=r"(r3) : "r"(addr))
#define LDSM_X4_T(r0, r1, r2, r3, addr) \
    asm volatile("ldmatrix.sync.aligned.m8n8.x4.trans.shared.b16 {%0,%1,%2,%3}, [%4];" \
                 : "=r"(r0), "=r"(r1), "=r"(r2), "=r"(r3) : "r"(addr))
#define LDSM_X2(r0, r1, addr) \
    asm volatile("ldmatrix.sync.aligned.m8n8.x2.shared.b16 {%0,%1}, [%2];" \
                 : "=r"(r0), "=r"(r1) : "r"(addr))
__device__ __forceinline__ void mma16816(float* c, uint32_t a0, uint32_t a1, uint32_t a2, uint32_t a3,
                                         uint32_t b0, uint32_t b1) {
    asm volatile(
        "mma.sync.aligned.m16n8k16.row.col.f32.bf16.bf16.f32 "
        "{%0,%1,%2,%3}, {%4,%5,%6,%7}, {%8,%9}, {%0,%1,%2,%3};"
        : "+f"(c[0]), "+f"(c[1]), "+f"(c[2]), "+f"(c[3])
        : "r"(a0), "r"(a1), "r"(a2), "r"(a3), "r"(b0), "r"(b1));
}
__device__ __forceinline__ void cpa16(uint32_t dst, const void* src) {
    asm volatile("cp.async.cg.shared.global [%0], [%1], 16;" :: "r"(dst), "l"(src));
}
#define CP_COMMIT() asm volatile("cp.async.commit_group;")
#define CP_WAIT1()  asm volatile("cp.async.wait_group 1;")
#define CP_WAIT0()  asm volatile("cp.async.wait_group 0;")

__device__ __forceinline__ void split2(float v, __nv_bfloat16& h, __nv_bfloat16& l) {
    h = __float2bfloat16(v);
    l = __float2bfloat16(v - __bfloat162float(h));
}
__device__ __forceinline__ uint32_t pk2(float e, float o) {
    __nv_bfloat162 v(__float2bfloat16(e), __float2bfloat16(o));
    return *(uint32_t*)&v;
}

// =====================  bf16 hi/lo pipelined tensor-core GEMM  ================
#define STAGE_BYTES 65536
#define SMEM_GEMM_BYTES (2 * STAGE_BYTES)

__device__ __forceinline__ void load_op(const __nv_bfloat16* hi, const __nv_bfloat16* lo,
                                        int rowBase, int ld, int k0,
                                        uint32_t smH, uint32_t smL, int tid) {
    #pragma unroll
    for (int it = 0; it < 4; it++) {
        int idx = it * 256 + tid;
        int r = idx >> 3, s = idx & 7;
        uint32_t sw = SWZ128(r * 128 + s * 16);
        cpa16(smH + sw, hi + (long)(rowBase + r) * ld + k0 + s * 8);
        cpa16(smL + sw, lo + (long)(rowBase + r) * ld + k0 + s * 8);
    }
}

// BIAS_MODE: 0 none, 1 per-row, 2 per-col. OUT_BF16 hi/lo out. PART: BN partials.
template<int BIAS_MODE, bool OUT_BF16, bool PART>
__global__ __launch_bounds__(256) void gemm_bf16(
    const __nv_bfloat16* __restrict__ Ahi, const __nv_bfloat16* __restrict__ Alo,
    const __nv_bfloat16* __restrict__ Bhi, const __nv_bfloat16* __restrict__ Blo,
    const float* __restrict__ bias,
    float* __restrict__ Cf, __nv_bfloat16* __restrict__ Chi, __nv_bfloat16* __restrict__ Clo,
    int ldA, int ldB, int ldC, int K,
    long sA, long sB, long sC)
{
    extern __shared__ __align__(1024) char sm[];
    const int bz = blockIdx.z;
    Ahi += (long)bz * sA; Alo += (long)bz * sA;
    Bhi += (long)bz * sB; Blo += (long)bz * sB;
    const long coff = (long)bz * sC;

    const int mBlock = blockIdx.y * 128;
    const int nBlock = blockIdx.x * 128;
    const int tid = threadIdx.x;
    const int wid = tid >> 5;
    const int lane = tid & 31;
    const uint32_t sbase = smem_u32(sm);

    const int mWarp = (wid >> 2) * 64;
    const int nWarp = (wid & 3) * 32;

    float acc[4][4][4];
    #pragma unroll
    for (int i = 0; i < 4; i++)
        #pragma unroll
        for (int j = 0; j < 4; j++)
            #pragma unroll
            for (int r = 0; r < 4; r++) acc[i][j][r] = 0.f;

    const int aRow = mWarp + (lane & 15);
    const int aKb  = (lane >> 4) << 4;
    const int bRow = nWarp + (lane & 7);
    const int bKb  = ((lane >> 3) & 1) << 4;

    const int nChunks = K >> 6;
    load_op(Ahi, Alo, mBlock, ldA, 0, sbase + 0,     sbase + 16384, tid);
    load_op(Bhi, Blo, nBlock, ldB, 0, sbase + 32768, sbase + 49152, tid);
    CP_COMMIT();

    for (int ch = 0; ch < nChunks; ch++) {
        if (ch + 1 < nChunks) {
            const uint32_t sb = sbase + ((ch + 1) & 1) * STAGE_BYTES;
            const int k0 = (ch + 1) << 6;
            load_op(Ahi, Alo, mBlock, ldA, k0, sb + 0,     sb + 16384, tid);
            load_op(Bhi, Blo, nBlock, ldB, k0, sb + 32768, sb + 49152, tid);
        }
        CP_COMMIT();
        CP_WAIT1();
        __syncthreads();

        const uint32_t st = sbase + (ch & 1) * STAGE_BYTES;
        #pragma unroll
        for (int ks = 0; ks < 4; ks++) {
            uint32_t aH[4][4], aL[4][4];
            #pragma unroll
            for (int mi = 0; mi < 4; mi++) {
                uint32_t sw = SWZ128((aRow + mi * 16) * 128 + ks * 32 + aKb);
                LDSM_X4(aH[mi][0], aH[mi][1], aH[mi][2], aH[mi][3], st + 0 + sw);
                LDSM_X4(aL[mi][0], aL[mi][1], aL[mi][2], aL[mi][3], st + 16384 + sw);
            }
            #pragma unroll
            for (int ni = 0; ni < 4; ni++) {
                uint32_t sw = SWZ128((bRow + ni * 8) * 128 + ks * 32 + bKb);
                uint32_t bH0, bH1, bL0, bL1;
                LDSM_X2(bH0, bH1, st + 32768 + sw);
                LDSM_X2(bL0, bL1, st + 49152 + sw);
                #pragma unroll
                for (int mi = 0; mi < 4; mi++) {
                    mma16816(acc[mi][ni], aH[mi][0], aH[mi][1], aH[mi][2], aH[mi][3], bH0, bH1);
                    mma16816(acc[mi][ni], aH[mi][0], aH[mi][1], aH[mi][2], aH[mi][3], bL0, bL1);
                    mma16816(acc[mi][ni], aL[mi][0], aL[mi][1], aL[mi][2], aL[mi][3], bH0, bH1);
                }
            }
        }
        __syncthreads();
    }

    const int mLane = lane >> 2;
    const int nLane = (lane & 3) * 2;
    #pragma unroll
    for (int mi = 0; mi < 4; mi++) {
        const int m0 = mBlock + mWarp + mi * 16 + mLane;
        float br0 = 0.f, br1 = 0.f;
        if (BIAS_MODE == 1) { br0 = bias[m0]; br1 = bias[m0 + 8]; }
        float s0 = 0.f, q0 = 0.f, s1 = 0.f, q1 = 0.f;
        #pragma unroll
        for (int ni = 0; ni < 4; ni++) {
            const int n = nBlock + nWarp + ni * 8 + nLane;
            float c0 = acc[mi][ni][0], c1 = acc[mi][ni][1];
            float c2 = acc[mi][ni][2], c3 = acc[mi][ni][3];
            if (BIAS_MODE == 1) { c0 += br0; c1 += br0; c2 += br1; c3 += br1; }
            if (BIAS_MODE == 2) {
                float bx = bias[n], by = bias[n + 1];
                c0 += bx; c1 += by; c2 += bx; c3 += by;
            }
            if (PART) {
                s0 += c0 + c1; q0 += c0 * c0 + c1 * c1;
                s1 += c2 + c3; q1 += c2 * c2 + c3 * c3;
            }
            if (OUT_BF16) {
                __nv_bfloat16 h0, h1, h2, h3, l0, l1, l2, l3;
                split2(c0, h0, l0); split2(c1, h1, l1);
                split2(c2, h2, l2); split2(c3, h3, l3);
                *(__nv_bfloat162*)&Chi[coff + (long)m0 * ldC + n]       = __nv_bfloat162(h0, h1);
                *(__nv_bfloat162*)&Clo[coff + (long)m0 * ldC + n]       = __nv_bfloat162(l0, l1);
                *(__nv_bfloat162*)&Chi[coff + (long)(m0 + 8) * ldC + n] = __nv_bfloat162(h2, h3);
                *(__nv_bfloat162*)&Clo[coff + (long)(m0 + 8) * ldC + n] = __nv_bfloat162(l2, l3);
            } else {
                float2 v0 = {c0, c1}, v1 = {c2, c3};
                *(float2*)&Cf[coff + (long)m0 * ldC + n]       = v0;
                *(float2*)&Cf[coff + (long)(m0 + 8) * ldC + n] = v1;
            }
        }
        if (PART) {
            s0 += __shfl_xor_sync(0xffffffffu, s0, 1);
            s0 += __shfl_xor_sync(0xffffffffu, s0, 2);
            q0 += __shfl_xor_sync(0xffffffffu, q0, 1);
            q0 += __shfl_xor_sync(0xffffffffu, q0, 2);
            s1 += __shfl_xor_sync(0xffffffffu, s1, 1);
            s1 += __shfl_xor_sync(0xffffffffu, s1, 2);
            q1 += __shfl_xor_sync(0xffffffffu, q1, 1);
            q1 += __shfl_xor_sync(0xffffffffu, q1, 2);
            if ((lane & 3) == 0) {
                const int slot = (bz * 32 + blockIdx.x) * 4 + (wid & 3);
                g_part_s[m0 * 1024 + slot] = s0;
                g_part_q[m0 * 1024 + slot] = q0;
                g_part_s[(m0 + 8) * 1024 + slot] = s1;
                g_part_q[(m0 + 8) * 1024 + slot] = q1;
            }
        }
    }
}

// =====================  fused attention  ======================================
#define ATT_SMEM (65536 + 2 * 65536)

__device__ __forceinline__ void att_load_chunk(int b, int m0, uint32_t buf, int tid) {
    const __nv_bfloat16* ph = g_phi_hi + ((long)b * MM + m0) * CI;
    const __nv_bfloat16* pl = g_phi_lo + ((long)b * MM + m0) * CI;
    const __nv_bfloat16* gh = g_gm_hi + ((long)b * MM + m0) * CI;
    const __nv_bfloat16* gl = g_gm_lo + ((long)b * MM + m0) * CI;
    #pragma unroll
    for (int it = 0; it < 4; it++) {
        int idx = it * 256 + tid;       // 1024: r(64) x s(16)
        int r = idx >> 4, s = idx & 15;
        uint32_t sw = SWZ256(r * 256 + s * 16);
        cpa16(buf + 0 + sw,     ph + (long)r * CI + s * 8);
        cpa16(buf + 16384 + sw, pl + (long)r * CI + s * 8);
        cpa16(buf + 32768 + sw, gh + (long)r * CI + s * 8);
        cpa16(buf + 49152 + sw, gl + (long)r * CI + s * 8);
    }
}

__global__ __launch_bounds__(256, 1) void attn_kernel() {
    extern __shared__ __align__(1024) char sm[];
    const int b = blockIdx.y;
    const int nBlock = blockIdx.x * 128;
    const int tid = threadIdx.x;
    const int wid = tid >> 5;
    const int lane = tid & 31;
    const uint32_t sbase = smem_u32(sm);
    const uint32_t TH = 0, TL = 32768, BUF0 = 65536;

    {
        const __nv_bfloat16* th = g_o3_hi + ((long)b * NN + nBlock) * 384;
        const __nv_bfloat16* tl = g_o3_lo + ((long)b * NN + nBlock) * 384;
        #pragma unroll
        for (int it = 0; it < 8; it++) {
            int idx = it * 256 + tid;
            int r = idx >> 4, s = idx & 15;
            uint32_t sw = SWZ256(r * 256 + s * 16);
            cpa16(sbase + TH + sw, th + (long)r * 384 + s * 8);
            cpa16(sbase + TL + sw, tl + (long)r * 384 + s * 8);
        }
    }
    att_load_chunk(b, 0, sbase + BUF0, tid);
    CP_COMMIT();

    float yacc[16][4];
    #pragma unroll
    for (int t = 0; t < 16; t++)
        #pragma unroll
        for (int r = 0; r < 4; r++) yacc[t][r] = 0.f;
    float rm0 = -1e30f, rm1 = -1e30f, rl0 = 0.f, rl1 = 0.f;

    const int aRowOff = wid * 16 + (lane & 15);
    const uint32_t aKb = (lane >> 4) << 4;
    const int bR = (lane & 7) + ((lane >> 4) & 1) * 8;
    const uint32_t bKb = ((lane >> 3) & 1) << 4;
    // trans-ldmatrix addressing for g [m][ci]: rows = m (k), col16B group = ci
    const int gRow = (lane & 7) + ((lane >> 3) & 1) * 8;
    const int gCol = (lane >> 4);

    for (int ch = 0; ch < 16; ch++) {
        if (ch < 15) {
            att_load_chunk(b, (ch + 1) * 64, sbase + BUF0 + ((ch + 1) & 1) * 65536, tid);
            CP_COMMIT();
            CP_WAIT1();
        } else {
            CP_WAIT0();
        }
        __syncthreads();
        const uint32_t bs = sbase + BUF0 + (ch & 1) * 65536;

        // ---- S = theta . phi^T ----
        float sacc[8][4];
        #pragma unroll
        for (int j = 0; j < 8; j++)
            #pragma unroll
            for (int r = 0; r < 4; r++) sacc[j][r] = 0.f;

        #pragma unroll
        for (int ks = 0; ks < 8; ks++) {
            uint32_t aH0, aH1, aH2, aH3, aL0, aL1, aL2, aL3;
            uint32_t swA = SWZ256(aRowOff * 256 + ks * 32 + aKb);
            LDSM_X4(aH0, aH1, aH2, aH3, sbase + TH + swA);
            LDSM_X4(aL0, aL1, aL2, aL3, sbase + TL + swA);
            #pragma unroll
            for (int jp = 0; jp < 4; jp++) {
                uint32_t swB = SWZ256((jp * 16 + bR) * 256 + ks * 32 + bKb);
                uint32_t bh0, bh1, bh2, bh3, bl0, bl1, bl2, bl3;
                LDSM_X4(bh0, bh1, bh2, bh3, bs + 0 + swB);
                LDSM_X4(bl0, bl1, bl2, bl3, bs + 16384 + swB);
                mma16816(sacc[2 * jp],     aH0, aH1, aH2, aH3, bh0, bh1);
                mma16816(sacc[2 * jp],     aH0, aH1, aH2, aH3, bl0, bl1);
                mma16816(sacc[2 * jp],     aL0, aL1, aL2, aL3, bh0, bh1);
                mma16816(sacc[2 * jp + 1], aH0, aH1, aH2, aH3, bh2, bh3);
                mma16816(sacc[2 * jp + 1], aH0, aH1, aH2, aH3, bl2, bl3);
                mma16816(sacc[2 * jp + 1], aL0, aL1, aL2, aL3, bh2, bh3);
            }
        }

        // ---- online softmax ----
        float cm0 = -1e30f, cm1 = -1e30f;
        #pragma unroll
        for (int j = 0; j < 8; j++) {
            cm0 = fmaxf(cm0, fmaxf(sacc[j][0], sacc[j][1]));
            cm1 = fmaxf(cm1, fmaxf(sacc[j][2], sacc[j][3]));
        }
        cm0 = fmaxf(cm0, __shfl_xor_sync(0xffffffffu, cm0, 1));
        cm0 = fmaxf(cm0, __shfl_xor_sync(0xffffffffu, cm0, 2));
        cm1 = fmaxf(cm1, __shfl_xor_sync(0xffffffffu, cm1, 1));
        cm1 = fmaxf(cm1, __shfl_xor_sync(0xffffffffu, cm1, 2));
        const float nm0 = fmaxf(rm0, cm0);
        const float nm1 = fmaxf(rm1, cm1);
        const float al0 = __expf(rm0 - nm0);
        const float al1 = __expf(rm1 - nm1);

        uint32_t pH[8][2], pL[8][2];
        float ps0 = 0.f, ps1 = 0.f;
        #pragma unroll
        for (int j = 0; j < 8; j++) {
            float e0 = __expf(sacc[j][0] - nm0);
            float e1 = __expf(sacc[j][1] - nm0);
            float e2 = __expf(sacc[j][2] - nm1);
            float e3 = __expf(sacc[j][3] - nm1);
            ps0 += e0 + e1; ps1 += e2 + e3;
            float h0 = __bfloat162float(__float2bfloat16(e0));
            float h1 = __bfloat162float(__float2bfloat16(e1));
            float h2 = __bfloat162float(__float2bfloat16(e2));
            float h3 = __bfloat162float(__float2bfloat16(e3));
            pH[j][0] = pk2(e0, e1);
            pH[j][1] = pk2(e2, e3);
            pL[j][0] = pk2(e0 - h0, e1 - h1);
            pL[j][1] = pk2(e2 - h2, e3 - h3);
        }
        ps0 += __shfl_xor_sync(0xffffffffu, ps0, 1);
        ps0 += __shfl_xor_sync(0xffffffffu, ps0, 2);
        ps1 += __shfl_xor_sync(0xffffffffu, ps1, 1);
        ps1 += __shfl_xor_sync(0xffffffffu, ps1, 2);
        rl0 = rl0 * al0 + ps0;
        rl1 = rl1 * al1 + ps1;
        rm0 = nm0; rm1 = nm1;
        #pragma unroll
        for (int t = 0; t < 16; t++) {
            yacc[t][0] *= al0; yacc[t][1] *= al0;
            yacc[t][2] *= al1; yacc[t][3] *= al1;
        }

        // ---- y += P . g  (g stored [m][ci], trans-ldmatrix B-frags) ----
        #pragma unroll
        for (int kk = 0; kk < 4; kk++) {
            const uint32_t ah0 = pH[2 * kk][0], ah1 = pH[2 * kk][1];
            const uint32_t ah2 = pH[2 * kk + 1][0], ah3 = pH[2 * kk + 1][1];
            const uint32_t al0r = pL[2 * kk][0], al1r = pL[2 * kk][1];
            const uint32_t al2r = pL[2 * kk + 1][0], al3r = pL[2 * kk + 1][1];
            #pragma unroll
            for (int t2 = 0; t2 < 8; t2++) {
                uint32_t swG = SWZ256((kk * 16 + gRow) * 256 + (2 * t2 + gCol) * 16);
                uint32_t gh0, gh1, gh2, gh3, gl0, gl1, gl2, gl3;
                LDSM_X4_T(gh0, gh1, gh2, gh3, bs + 32768 + swG);
                LDSM_X4_T(gl0, gl1, gl2, gl3, bs + 49152 + swG);
                mma16816(yacc[2 * t2],     ah0, ah1, ah2, ah3, gh0, gh1);
                mma16816(yacc[2 * t2],     ah0, ah1, ah2, ah3, gl0, gl1);
                mma16816(yacc[2 * t2],     al0r, al1r, al2r, al3r, gh0, gh1);
                mma16816(yacc[2 * t2 + 1], ah0, ah1, ah2, ah3, gh2, gh3);
                mma16816(yacc[2 * t2 + 1], ah0, ah1, ah2, ah3, gl2, gl3);
                mma16816(yacc[2 * t2 + 1], al0r, al1r, al2r, al3r, gh2, gh3);
            }
        }
        __syncthreads();
    }

    // ---- epilogue ----
    const float inv0 = 1.f / rl0;
    const float inv1 = 1.f / rl1;
    const int n0 = nBlock + wid * 16 + (lane >> 2);
    const int cB = (lane & 3) * 2;
    #pragma unroll
    for (int t = 0; t < 16; t++) {
        const int ci = t * 8 + cB;
        float c0 = yacc[t][0] * inv0, c1 = yacc[t][1] * inv0;
        float c2 = yacc[t][2] * inv1, c3 = yacc[t][3] * inv1;
        __nv_bfloat16 h0, h1, h2, h3, l0, l1, l2, l3;
        split2(c0, h0, l0); split2(c1, h1, l1);
        split2(c2, h2, l2); split2(c3, h3, l3);
        const long o0 = ((long)b * NN + n0) * CI + ci;
        const long o1 = ((long)b * NN + n0 + 8) * CI + ci;
        *(__nv_bfloat162*)&g_y_hi[o0] = __nv_bfloat162(h0, h1);
        *(__nv_bfloat162*)&g_y_lo[o0] = __nv_bfloat162(l0, l1);
        *(__nv_bfloat162*)&g_y_hi[o1] = __nv_bfloat162(h2, h3);
        *(__nv_bfloat162*)&g_y_lo[o1] = __nv_bfloat162(l2, l3);
    }
}

// ---------------- x transpose + hi/lo convert ----------------------------------
__global__ __launch_bounds__(256) void transpose_x(const float* __restrict__ x) {
    __shared__ float t[32][33];
    const int b = blockIdx.z;
    const int n0 = blockIdx.x * 32, c0 = blockIdx.y * 32;
    const int tx = threadIdx.x, ty = threadIdx.y;
    #pragma unroll
    for (int i = ty; i < 32; i += 8)
        t[i][tx] = x[((long)b * CC + c0 + i) * NN + n0 + tx];
    __syncthreads();
    #pragma unroll
    for (int i = ty; i < 32; i += 8) {
        float v = t[tx][i];
        __nv_bfloat16 h, l;
        split2(v, h, l);
        const long o = ((long)b * NN + n0 + i) * CC + c0 + tx;
        g_xT_hi[o] = h;
        g_xT_lo[o] = l;
    }
}

// ---------------- weight convert ------------------------------------------------
__global__ __launch_bounds__(256) void convert_w(
    const float* __restrict__ tw, const float* __restrict__ pw, const float* __restrict__ gw,
    const float* __restrict__ tb, const float* __restrict__ pb, const float* __restrict__ gb,
    const float* __restrict__ Ww)
{
    const int i = blockIdx.x * 256 + threadIdx.x;
    const int TOT1 = 384 * CC;
    const int TOT2 = TOT1 + CC * CI;
    if (i < TOT1) {
        int o = i / CC, c = i % CC;
        float v = (o < 128) ? tw[o * CC + c] : (o < 256) ? pw[(o - 128) * CC + c] : gw[(o - 256) * CC + c];
        __nv_bfloat16 h, l; split2(v, h, l);
        g_w_hi[i] = h; g_w_lo[i] = l;
    } else if (i < TOT2) {
        float v = Ww[i - TOT1];
        __nv_bfloat16 h, l; split2(v, h, l);
        g_w_hi[i] = h; g_w_lo[i] = l;
    }
    if (i < 384)
        g_bias384[i] = (i < 128) ? tb[i] : (i < 256) ? pb[i - 128] : gb[i - 256];
}

// ---------------- 2x2 maxpool (both outputs [m][ci], coalesced) -----------------
__device__ __forceinline__ void ld4bf(const __nv_bfloat16* p, float* out) {
    uint2 u = *(const uint2*)p;
    __nv_bfloat162 a = *(__nv_bfloat162*)&u.x;
    __nv_bfloat162 bq = *(__nv_bfloat162*)&u.y;
    out[0] = __bfloat162float(a.x); out[1] = __bfloat162float(a.y);
    out[2] = __bfloat162float(bq.x); out[3] = __bfloat162float(bq.y);
}

__global__ __launch_bounds__(256) void pool_kernel() {
    const int i = blockIdx.x * 256 + threadIdx.x;   // BB*MM*32
    if (i >= BB * MM * 32) return;
    const int c4 = (i & 31) << 2;
    const int m  = (i >> 5) & (MM - 1);
    const int b  = i >> 15;
    const int hp = m >> 5, wp = m & 31;
    const int n0 = hp * 128 + wp * 2;
    const long rb = (long)b * NN;
    const long o = ((long)b * MM + m) * CI + c4;

    #pragma unroll
    for (int which = 0; which < 2; which++) {
        const int col = (which == 0 ? 128 : 256) + c4;
        float mx[4] = {-1e30f, -1e30f, -1e30f, -1e30f};
        #pragma unroll
        for (int rr = 0; rr < 4; rr++) {
            const int n = n0 + (rr & 1) + (rr >> 1) * 64;
            const long base = (rb + n) * 384 + col;
            float vh[4], vl[4];
            ld4bf(&g_o3_hi[base], vh);
            ld4bf(&g_o3_lo[base], vl);
            #pragma unroll
            for (int e = 0; e < 4; e++) mx[e] = fmaxf(mx[e], vh[e] + vl[e]);
        }
        __nv_bfloat16 h[4], l[4];
        #pragma unroll
        for (int e = 0; e < 4; e++) split2(mx[e], h[e], l[e]);
        __nv_bfloat16* dh = (which == 0) ? g_phi_hi : g_gm_hi;
        __nv_bfloat16* dl = (which == 0) ? g_phi_lo : g_gm_lo;
        *(__nv_bfloat162*)&dh[o]     = __nv_bfloat162(h[0], h[1]);
        *(__nv_bfloat162*)&dh[o + 2] = __nv_bfloat162(h[2], h[3]);
        *(__nv_bfloat162*)&dl[o]     = __nv_bfloat162(l[0], l[1]);
        *(__nv_bfloat162*)&dl[o + 2] = __nv_bfloat162(l[2], l[3]);
    }
}

// ---------------- BN reduce from K4 partials (deterministic) -------------------
__global__ __launch_bounds__(256) void bn_reduce(const float* __restrict__ gamma,
                                                 const float* __restrict__ beta) {
    const int c = blockIdx.x;
    const int t = threadIdx.x;
    double s = 0.0, q = 0.0;
    #pragma unroll
    for (int i = t; i < 1024; i += 256) {
        s += (double)g_part_s[c * 1024 + i];
        q += (double)g_part_q[c * 1024 + i];
    }
    __shared__ double ss[256], sz[256];
    ss[t] = s; sz[t] = q;
    __syncthreads();
    for (int st = 128; st; st >>= 1) {
        if (t < st) { ss[t] += ss[t + st]; sz[t] += sz[t + st]; }
        __syncthreads();
    }
    if (t == 0) {
        const double cnt = 1.0 / (double)(BB * NN);
        const double mean = ss[0] * cnt;
        const double var  = sz[0] * cnt - mean * mean;
        const double inv  = 1.0 / sqrt(var + 1e-5);
        const float sc = gamma[c] * (float)inv;
        g_scale[c] = sc;
        g_shift[c] = beta[c] - (float)mean * sc;
    }
}

// ---------------- apply BN + residual ------------------------------------------
__global__ __launch_bounds__(256) void final_kernel(const float* __restrict__ x,
                                                    float* __restrict__ out) {
    const long i = (long)blockIdx.x * 256 + threadIdx.x;
    const long e = i << 2;
    const int c = (int)((e >> 12) & (CC - 1));
    const float sc = g_scale[c], sh = g_shift[c];
    float4 wy = ((const float4*)g_wy)[i];
    float4 xv = ((const float4*)x)[i];
    float4 o;
    o.x = fmaf(wy.x, sc, sh) + xv.x;
    o.y = fmaf(wy.y, sc, sh) + xv.y;
    o.z = fmaf(wy.z, sc, sh) + xv.z;
    o.w = fmaf(wy.w, sc, sh) + xv.w;
    ((float4*)out)[i] = o;
}

// ------------------------------------------------------------------------------
extern "C" void kernel_launch(void* const* d_in, const int* in_sizes, int n_in,
                              void* d_out, int out_size) {
    (void)in_sizes; (void)n_in; (void)out_size;
    const float* x     = (const float*)d_in[0];
    const float* tw    = (const float*)d_in[1];
    const float* tb    = (const float*)d_in[2];
    const float* pw    = (const float*)d_in[3];
    const float* pb    = (const float*)d_in[4];
    const float* gw    = (const float*)d_in[5];
    const float* gb    = (const float*)d_in[6];
    const float* Ww    = (const float*)d_in[7];
    const float* Wb    = (const float*)d_in[8];
    const float* gamma = (const float*)d_in[9];
    const float* beta  = (const float*)d_in[10];
    float* out = (float*)d_out;

    __nv_bfloat16 *xTh, *xTl, *wh, *wl, *o3h, *o3l, *yh, *yl;
    float *wy, *bias384;
    cudaGetSymbolAddress((void**)&xTh, g_xT_hi);  cudaGetSymbolAddress((void**)&xTl, g_xT_lo);
    cudaGetSymbolAddress((void**)&wh,  g_w_hi);   cudaGetSymbolAddress((void**)&wl,  g_w_lo);
    cudaGetSymbolAddress((void**)&o3h, g_o3_hi);  cudaGetSymbolAddress((void**)&o3l, g_o3_lo);
    cudaGetSymbolAddress((void**)&yh,  g_y_hi);   cudaGetSymbolAddress((void**)&yl,  g_y_lo);
    cudaGetSymbolAddress((void**)&wy,  g_wy);
    cudaGetSymbolAddress((void**)&bias384, g_bias384);

    cudaFuncSetAttribute(gemm_bf16<2, true,  false>, cudaFuncAttributeMaxDynamicSharedMemorySize, SMEM_GEMM_BYTES);
    cudaFuncSetAttribute(gemm_bf16<1, false, true >, cudaFuncAttributeMaxDynamicSharedMemorySize, SMEM_GEMM_BYTES);
    cudaFuncSetAttribute(attn_kernel, cudaFuncAttributeMaxDynamicSharedMemorySize, ATT_SMEM);

    // P1: convert weights + biases
    convert_w<<<(384 * CC + CC * CI + 255) / 256, 256>>>(tw, pw, gw, tb, pb, gb, Ww);
    // P2: transpose + convert x -> xT [b][n][c]
    transpose_x<<<dim3(NN / 32, CC / 32, BB), dim3(32, 8)>>>(x);

    // K1: o3[b][n][o<384] = xT[n][c] . wcat[o][c]  (col bias), out bf16 hi/lo
    gemm_bf16<2, true, false><<<dim3(3, 32, BB), 256, SMEM_GEMM_BYTES>>>(
        xTh, xTl, wh, wl, bias384, nullptr, o3h, o3l,
        CC, CC, 384, CC, (long)NN * CC, 0, (long)NN * 384);

    // K2: maxpool -> phi [m][ci], gm [m][ci] (bf16 hi/lo, coalesced)
    pool_kernel<<<(BB * MM * 32 + 255) / 256, 256>>>();

    // K3: fused theta.phi^T -> softmax -> .g  ==> y [b][n][ci] bf16 hi/lo
    attn_kernel<<<dim3(NN / 128, BB), 256, ATT_SMEM>>>();

    // K4: wy[c][n] = Ww[c][ci] . y[n][ci]  (row bias Wb) + BN partial sums
    gemm_bf16<1, false, true><<<dim3(NN / 128, CC / 128, BB), 256, SMEM_GEMM_BYTES>>>(
        wh + 384 * CC, wl + 384 * CC, yh, yl, Wb, wy, nullptr, nullptr,
        CI, CI, NN, CI, 0, (long)NN * CI, (long)CC * NN);

    // K5: BN reduce from partials
    bn_reduce<<<CC, 256>>>(gamma, beta);

    // K6: apply BN + residual
    final_kernel<<<(BB * CC * NN) / 4 / 256, 256>>>(x, out);
}